// round 4
// baseline (speedup 1.0000x reference)
#include <cuda_runtime.h>

typedef unsigned long long ull;
typedef unsigned int uint;

__device__ __forceinline__ ull pack2(float lo, float hi) {
    ull v; asm("mov.b64 %0, {%1, %2};" : "=l"(v) : "f"(lo), "f"(hi)); return v;
}
__device__ __forceinline__ void unpack2(ull v, float& lo, float& hi) {
    asm("mov.b64 {%0, %1}, %2;" : "=f"(lo), "=f"(hi) : "l"(v));
}
__device__ __forceinline__ void ffma2(ull& d, ull a, ull b) {
    asm("fma.rn.f32x2 %0, %1, %2, %0;" : "+l"(d) : "l"(a), "l"(b));
}
__device__ __forceinline__ float tanhx(float x) {
    float y; asm("tanh.approx.f32 %0, %1;" : "=f"(y) : "f"(x)); return y;
}
__device__ __forceinline__ uint cvt_tf32(float x) {
    uint r; asm("cvt.rna.tf32.f32 %0, %1;" : "=r"(r) : "f"(x)); return r;
}
// Dice via tanh: dice(x) = x * fma(C2, tanh(fma(x, S2, MS2)), A2)
__device__ __forceinline__ float dice4(float x, float4 c) {
    return x * fmaf(c.y, tanhx(fmaf(x, c.z, c.w)), c.x);
}
// m16n8k8 tf32 warp MMA (A row-major, B col-major, fp32 accum)
__device__ __forceinline__ void mma16n8k8(float& d0, float& d1, float& d2, float& d3,
                                          uint a0, uint a1, uint a2, uint a3,
                                          uint b0, uint b1) {
    asm("mma.sync.aligned.m16n8k8.row.col.f32.tf32.tf32.f32 "
        "{%0,%1,%2,%3}, {%4,%5,%6,%7}, {%8,%9}, {%0,%1,%2,%3};"
        : "+f"(d0), "+f"(d1), "+f"(d2), "+f"(d3)
        : "r"(a0), "r"(a1), "r"(a2), "r"(a3), "r"(b0), "r"(b1));
}

// Shared memory layout (floats), dynamic:
static constexpr int DROW   = 84;               // D row stride (conflict-free: 84 mod 32 = 20)
static constexpr int O_DSH  = 0;                // Dsh [208][84] tf32 bits  (17472)
static constexpr int O_KSH  = O_DSH + 208*DROW; // ksh [200][12]            (2400)
static constexpr int O_W1T  = O_KSH + 2400;     // W1 tf32 [80][40]         (3200)
static constexpr int O_MP   = O_W1T + 3200;     // Mp channel-packed        (960)
static constexpr int O_D0C  = O_MP + 960;       // d0c float4[80]           (320)
static constexpr int O_D1C  = O_D0C + 320;      // d1c float4[40]           (160)
static constexpr int O_BF   = O_D1C + 160;      // Bf [80]                  (80)
static constexpr int O_B1D  = O_BF + 80;        // b1d [40]                 (40)
static constexpr int O_SC   = O_B1D + 40;       // sc [208]                 (208)
static constexpr int O_PSUM = O_SC + 208;       // psum [96]                (96)
static constexpr int O_QS   = O_PSUM + 96;      // qs [12]                  (12)
static constexpr int O_SC0  = O_QS + 12;        // score0                   (4 pad)
static constexpr int SMEM_FLOATS = O_SC0 + 4;
static constexpr int SMEM_BYTES  = SMEM_FLOATS * 4;  // 99824 B -> 2 CTAs/SM

__global__ void __launch_bounds__(256) din_kernel(
    const float* __restrict__ query, const float* __restrict__ keys,
    const float* __restrict__ W0, const float* __restrict__ b0,
    const float* __restrict__ W1, const float* __restrict__ b1,
    const float* __restrict__ alpha0, const float* __restrict__ alpha1,
    const float* __restrict__ mm0, const float* __restrict__ mv0,
    const float* __restrict__ mm1, const float* __restrict__ mv1,
    const float* __restrict__ ak, const float* __restrict__ ab,
    float* __restrict__ out)
{
    extern __shared__ __align__(16) float smf[];
    float*  Dsh  = smf + O_DSH;
    float*  ksh  = smf + O_KSH;
    float*  W1t  = smf + O_W1T;
    float*  Mp   = smf + O_MP;
    float4* d0c  = (float4*)(smf + O_D0C);
    float4* d1c  = (float4*)(smf + O_D1C);
    float*  Bf   = smf + O_BF;
    float*  b1d  = smf + O_B1D;
    float*  sc   = smf + O_SC;
    float*  psum = smf + O_PSUM;
    float*  qs   = smf + O_QS;

    const int tid  = threadIdx.x;
    const int b    = blockIdx.x;
    const int wid  = tid >> 5;
    const int lane = tid & 31;
    const float EPS = 1e-9f;

    if (tid < 12) qs[tid] = query[b * 12 + tid];
    if (tid == 0) smf[O_SC0] = ab[0];
    __syncthreads();  // qs needed below

    // ===================== Phase A: cooperative precompute =====================
    {
        const float4* gk = (const float4*)(keys + (size_t)b * 2400);
        float4* sk = (float4*)ksh;
        for (int i = tid; i < 600; i += 256) sk[i] = gk[i];
    }
    // W1 rounded to tf32 once
    for (int i = tid; i < 3200; i += 256)
        W1t[i] = __uint_as_float(cvt_tf32(W1[i]));
    // Mp channel-packed: floats at [op*24 + 2i + half] = M[2op+half][i]
    // where M[ch][i] = W0[12+i][ch] - W0[24+i][ch] + q_i * W0[36+i][ch]
    for (int idx = tid; idx < 960; idx += 256) {
        int op = idx / 24, rem = idx % 24;
        int i = rem >> 1, ch = 2 * op + (rem & 1);
        Mp[idx] = W0[(12 + i) * 80 + ch] - W0[(24 + i) * 80 + ch]
                + qs[i] * W0[(36 + i) * 80 + ch];
    }
    // base + dice0 constants
    if (tid < 80) {
        int o = tid;
        float s = b0[o];
        #pragma unroll
        for (int i = 0; i < 12; ++i)
            s += qs[i] * (W0[i * 80 + o] + W0[(24 + i) * 80 + o]);
        Bf[o] = s;
        float a  = alpha0[o];
        float c2 = 0.5f * (1.0f - a);
        float s2 = 0.5f * rsqrtf(mv0[o] + EPS);
        d0c[o] = make_float4(a + c2, c2, s2, -mm0[o] * s2);
    }
    // dice1 constants with ak folded; MS2' absorbs b1 shift (z uses raw acc c)
    if (tid < 40) {
        int o = tid;
        float a  = alpha1[o];
        float kk = ak[o];
        float c2 = 0.5f * (1.0f - a);
        float s2 = 0.5f * rsqrtf(mv1[o] + EPS);
        d1c[o] = make_float4((a + c2) * kk, c2 * kk, s2, (b1[o] - mm1[o]) * s2);
        b1d[o] = b1[o];
    }
    // zero D pad rows (200..207) and init scores
    for (int i = tid; i < 8 * DROW; i += 256) Dsh[200 * DROW + i] = 0.0f;
    if (tid < 208) sc[tid] = (tid < 200) ? smf[O_SC0] : 0.0f;
    __syncthreads();

    // ===================== Phase B: layer0 + dice0 -> Dsh (tf32) ================
    // 200 threads, 1 position each, channel-packed f32x2.
    if (tid < 200) {
        const int t = tid;
        ull kd[12];
        #pragma unroll
        for (int i = 0; i < 12; ++i) {
            float kv = ksh[t * 12 + i];
            kd[i] = pack2(kv, kv);
        }
        float* drow = Dsh + t * DROW;
        #pragma unroll 2
        for (int op = 0; op < 40; ++op) {
            const int ch = 2 * op;
            ull acc = ((const ull*)Bf)[op];  // (base_ch, base_ch+1)
            const ulonglong2* mp = ((const ulonglong2*)Mp) + op * 6;
            #pragma unroll
            for (int i2 = 0; i2 < 6; ++i2) {
                ulonglong2 m = mp[i2];
                ffma2(acc, kd[2 * i2],     m.x);
                ffma2(acc, kd[2 * i2 + 1], m.y);
            }
            float x0, x1;
            unpack2(acc, x0, x1);
            float d0v = dice4(x0, d0c[ch]);
            float d1v = dice4(x1, d0c[ch + 1]);
            *(float2*)(drow + ch) = make_float2(
                __uint_as_float(cvt_tf32(d0v)), __uint_as_float(cvt_tf32(d1v)));
        }
    }
    __syncthreads();

    // ===================== Phase C: layer1 GEMM via tf32 HMMA + dice1 epilogue ==
    // h[208 x 40] = Dsh[208 x 80] @ W1t[80 x 40]; tiles: 13 pos-tiles (16) x 5 j-tiles (8)
    {
        const int g  = lane & 3;   // thread-in-group (col group)
        const int rw = lane >> 2;  // row / n within fragment

        for (int item = wid; item < 65; item += 8) {
            const int pt = item % 13, jt = item / 13;
            const int pr = pt * 16, j0 = jt * 8;

            // B fragments: 10 k-tiles x 2 regs; b0 = W1[kt*8+g][j0+rw], b1 = +4 k
            uint bf[10][2];
            #pragma unroll
            for (int kt = 0; kt < 10; ++kt) {
                int krow = kt * 8 + g;
                bf[kt][0] = __float_as_uint(W1t[krow * 40 + j0 + rw]);
                bf[kt][1] = __float_as_uint(W1t[(krow + 4) * 40 + j0 + rw]);
            }

            float e0 = 0.f, e1 = 0.f, e2 = 0.f, e3 = 0.f;  // even-k acc
            float o0 = 0.f, o1 = 0.f, o2 = 0.f, o3 = 0.f;  // odd-k acc
            const float* da = Dsh + (pr + rw) * DROW;
            const float* db = da + 8 * DROW;
            #pragma unroll
            for (int kt = 0; kt < 10; kt += 2) {
                int c0i = kt * 8 + g;
                uint a0 = __float_as_uint(da[c0i]);
                uint a1 = __float_as_uint(db[c0i]);
                uint a2 = __float_as_uint(da[c0i + 4]);
                uint a3 = __float_as_uint(db[c0i + 4]);
                mma16n8k8(e0, e1, e2, e3, a0, a1, a2, a3, bf[kt][0], bf[kt][1]);
                int c1i = c0i + 8;
                uint a4 = __float_as_uint(da[c1i]);
                uint a5 = __float_as_uint(db[c1i]);
                uint a6 = __float_as_uint(da[c1i + 4]);
                uint a7 = __float_as_uint(db[c1i + 4]);
                mma16n8k8(o0, o1, o2, o3, a4, a5, a6, a7, bf[kt+1][0], bf[kt+1][1]);
            }
            float c0 = e0 + o0, c1 = e1 + o1, c2 = e2 + o2, c3 = e3 + o3;
            // acc layout: c0=h[pr+rw][ja], c1=h[pr+rw][ja+1], c2=h[pr+rw+8][ja], c3=...[ja+1]
            const int ja = j0 + 2 * g;
            float4 ca = d1c[ja], cb = d1c[ja + 1];
            float  ba = b1d[ja], bb = b1d[ja + 1];
            // contribution = (c + b1) * fma(C2k, tanh(fma(c, S2, MS2')), A2k)
            float s0 = (c0 + ba) * fmaf(ca.y, tanhx(fmaf(c0, ca.z, ca.w)), ca.x)
                     + (c1 + bb) * fmaf(cb.y, tanhx(fmaf(c1, cb.z, cb.w)), cb.x);
            float s1 = (c2 + ba) * fmaf(ca.y, tanhx(fmaf(c2, ca.z, ca.w)), ca.x)
                     + (c3 + bb) * fmaf(cb.y, tanhx(fmaf(c3, cb.z, cb.w)), cb.x);
            // reduce over the 4 lanes sharing this row (xor 1, xor 2)
            s0 += __shfl_xor_sync(0xFFFFFFFF, s0, 1);
            s0 += __shfl_xor_sync(0xFFFFFFFF, s0, 2);
            s1 += __shfl_xor_sync(0xFFFFFFFF, s1, 1);
            s1 += __shfl_xor_sync(0xFFFFFFFF, s1, 2);
            if (g == 0) {
                atomicAdd(sc + pr + rw, s0);
                atomicAdd(sc + pr + rw + 8, s1);
            }
        }
    }
    __syncthreads();

    // ===================== Final: out[b][e] = sum_t sc[t] * keys[b][t][e] ======
    // (UNMASKED scores, reproducing the reference bug faithfully)
    if (tid < 96) {
        int e = tid % 12;
        int c = tid / 12;     // 8 chunks of 25 positions
        float acc = 0.0f;
        int t0 = c * 25;
        #pragma unroll 5
        for (int t2 = t0; t2 < t0 + 25; ++t2)
            acc = fmaf(sc[t2], ksh[t2 * 12 + e], acc);
        psum[tid] = acc;
    }
    __syncthreads();
    if (tid < 12) {
        float acc = 0.0f;
        #pragma unroll
        for (int c = 0; c < 8; ++c) acc += psum[c * 12 + tid];
        out[b * 12 + tid] = acc;
    }
}

extern "C" void kernel_launch(void* const* d_in, const int* in_sizes, int n_in,
                              void* d_out, int out_size) {
    const float* query  = (const float*)d_in[0];
    const float* keys   = (const float*)d_in[1];
    // d_in[2] = mask (bool) -- intentionally unused: reference overwrites the
    // masked scores and matmuls the UNMASKED scores (bug reproduced faithfully)
    const float* W0     = (const float*)d_in[3];
    const float* b0     = (const float*)d_in[4];
    const float* W1     = (const float*)d_in[5];
    const float* b1     = (const float*)d_in[6];
    const float* alpha0 = (const float*)d_in[7];
    const float* alpha1 = (const float*)d_in[8];
    const float* mm0    = (const float*)d_in[9];
    const float* mv0    = (const float*)d_in[10];
    const float* mm1    = (const float*)d_in[11];
    const float* mv1    = (const float*)d_in[12];
    const float* ak     = (const float*)d_in[13];
    const float* ab     = (const float*)d_in[14];
    float* out = (float*)d_out;

    // idempotent, not a stream op -> graph-capture safe
    cudaFuncSetAttribute(din_kernel, cudaFuncAttributeMaxDynamicSharedMemorySize,
                         SMEM_BYTES);

    int B = out_size / 12;  // [B, 1, 12]
    din_kernel<<<B, 256, SMEM_BYTES>>>(query, keys, W0, b0, W1, b1, alpha0, alpha1,
                                       mm0, mv0, mm1, mv1, ak, ab, out);
}

// round 5
// speedup vs baseline: 1.0228x; 1.0228x over previous
#include <cuda_runtime.h>

typedef unsigned long long ull;
typedef unsigned int uint;

__device__ __forceinline__ ull pack2(float lo, float hi) {
    ull v; asm("mov.b64 %0, {%1, %2};" : "=l"(v) : "f"(lo), "f"(hi)); return v;
}
__device__ __forceinline__ void unpack2(ull v, float& lo, float& hi) {
    asm("mov.b64 {%0, %1}, %2;" : "=f"(lo), "=f"(hi) : "l"(v));
}
__device__ __forceinline__ void ffma2(ull& d, ull a, ull b) {
    asm("fma.rn.f32x2 %0, %1, %2, %0;" : "+l"(d) : "l"(a), "l"(b));
}
__device__ __forceinline__ float tanhx(float x) {
    float y; asm("tanh.approx.f32 %0, %1;" : "=f"(y) : "f"(x)); return y;
}
__device__ __forceinline__ uint cvt_tf32(float x) {
    uint r; asm("cvt.rna.tf32.f32 %0, %1;" : "=r"(r) : "f"(x)); return r;
}
// Dice via tanh: dice(x) = x * fma(C2, tanh(fma(x, S2, MS2)), A2)
__device__ __forceinline__ float dice4(float x, float4 c) {
    return x * fmaf(c.y, tanhx(fmaf(x, c.z, c.w)), c.x);
}
// m16n8k8 tf32 warp MMA (A row-major, B col-major, fp32 accum)
__device__ __forceinline__ void mma16n8k8(float& d0, float& d1, float& d2, float& d3,
                                          uint a0, uint a1, uint a2, uint a3,
                                          uint b0, uint b1) {
    asm("mma.sync.aligned.m16n8k8.row.col.f32.tf32.tf32.f32 "
        "{%0,%1,%2,%3}, {%4,%5,%6,%7}, {%8,%9}, {%0,%1,%2,%3};"
        : "+f"(d0), "+f"(d1), "+f"(d2), "+f"(d3)
        : "r"(a0), "r"(a1), "r"(a2), "r"(a3), "r"(b0), "r"(b1));
}

// column interleave within each 8-col block: slot(c) = (c&~7) + 2*(c&3) + ((c>>2)&1)
// => columns (8k+g, 8k+g+4) land at adjacent slots (8k+2g, 8k+2g+1)
__device__ __forceinline__ int slot_of(int c) {
    return (c & ~7) + 2 * (c & 3) + ((c >> 2) & 1);
}

// Shared memory layout (floats), dynamic:
static constexpr int DROW   = 84;               // D row stride (pad for conflict spread)
static constexpr int O_DSH  = 0;                // Dsh [208][84] tf32 bits  (17472)
static constexpr int O_KSH  = O_DSH + 208*DROW; // ksh [200][12]            (2400)
static constexpr int O_W1T  = O_KSH + 2400;     // W1 tf32 [80][40]         (3200)
static constexpr int O_MP   = O_W1T + 3200;     // Mp pair-packed           (960)
static constexpr int O_D0C  = O_MP + 960;       // d0c float4[80] (slot ord)(320)
static constexpr int O_D1C  = O_D0C + 320;      // d1c float4[40]           (160)
static constexpr int O_BF   = O_D1C + 160;      // Bfi [80] (slot order)    (80)
static constexpr int O_B1D  = O_BF + 80;        // b1d [40]                 (40)
static constexpr int O_SC   = O_B1D + 40;       // sc [208]                 (208)
static constexpr int O_PSUM = O_SC + 208;       // psum [96]                (96)
static constexpr int O_QS   = O_PSUM + 96;      // qs [12]                  (12)
static constexpr int O_SC0  = O_QS + 12;        // score0                   (4 pad)
static constexpr int SMEM_FLOATS = O_SC0 + 4;
static constexpr int SMEM_BYTES  = SMEM_FLOATS * 4;  // 99824 B -> 2 CTAs/SM

__global__ void __launch_bounds__(256, 2) din_kernel(
    const float* __restrict__ query, const float* __restrict__ keys,
    const float* __restrict__ W0, const float* __restrict__ b0,
    const float* __restrict__ W1, const float* __restrict__ b1,
    const float* __restrict__ alpha0, const float* __restrict__ alpha1,
    const float* __restrict__ mm0, const float* __restrict__ mv0,
    const float* __restrict__ mm1, const float* __restrict__ mv1,
    const float* __restrict__ ak, const float* __restrict__ ab,
    float* __restrict__ out)
{
    extern __shared__ __align__(16) float smf[];
    float*  Dsh  = smf + O_DSH;
    float*  ksh  = smf + O_KSH;
    float*  W1t  = smf + O_W1T;
    float*  Mp   = smf + O_MP;
    float4* d0c  = (float4*)(smf + O_D0C);   // indexed by 2*bp (+1): slot-pair order
    float4* d1c  = (float4*)(smf + O_D1C);
    float*  Bfi  = smf + O_BF;               // slot order
    float*  b1d  = smf + O_B1D;
    float*  sc   = smf + O_SC;
    float*  psum = smf + O_PSUM;
    float*  qs   = smf + O_QS;

    const int tid  = threadIdx.x;
    const int b    = blockIdx.x;
    const int wid  = tid >> 5;
    const int lane = tid & 31;
    const float EPS = 1e-9f;

    if (tid < 12) qs[tid] = query[b * 12 + tid];
    if (tid == 0) smf[O_SC0] = ab[0];
    __syncthreads();  // qs needed below

    // ===================== Phase A: cooperative precompute =====================
    {
        const float4* gk = (const float4*)(keys + (size_t)b * 2400);
        float4* sk = (float4*)ksh;
        for (int i = tid; i < 600; i += 256) sk[i] = gk[i];
    }
    // W1 rounded to tf32 once (natural row-major [80][40])
    for (int i = tid; i < 3200; i += 256)
        W1t[i] = __uint_as_float(cvt_tf32(W1[i]));
    // Mp: pair-packed M for f32x2. bp in [0,40): chA = 8*(bp>>2)+(bp&3), chB = chA+4.
    // float at Mp[bp*24 + 2i + half] = M[chA + 4*half][i]
    // where M[ch][i] = W0[12+i][ch] - W0[24+i][ch] + q_i * W0[36+i][ch]
    for (int idx = tid; idx < 960; idx += 256) {
        int bp = idx / 24, rem = idx % 24;
        int i = rem >> 1, half = rem & 1;
        int ch = 8 * (bp >> 2) + (bp & 3) + 4 * half;
        Mp[idx] = W0[(12 + i) * 80 + ch] - W0[(24 + i) * 80 + ch]
                + qs[i] * W0[(36 + i) * 80 + ch];
    }
    // base + dice0 constants, stored at slot(o) so Phase B reads pairs linearly
    if (tid < 80) {
        int o = tid;
        float s = b0[o];
        #pragma unroll
        for (int i = 0; i < 12; ++i)
            s += qs[i] * (W0[i * 80 + o] + W0[(24 + i) * 80 + o]);
        int sl = slot_of(o);
        Bfi[sl] = s;
        float a  = alpha0[o];
        float c2 = 0.5f * (1.0f - a);
        float s2 = 0.5f * rsqrtf(mv0[o] + EPS);
        d0c[sl] = make_float4(a + c2, c2, s2, -mm0[o] * s2);
    }
    // dice1 constants with ak folded; MS2' absorbs b1 shift (z uses raw acc c)
    if (tid < 40) {
        int o = tid;
        float a  = alpha1[o];
        float kk = ak[o];
        float c2 = 0.5f * (1.0f - a);
        float s2 = 0.5f * rsqrtf(mv1[o] + EPS);
        d1c[o] = make_float4((a + c2) * kk, c2 * kk, s2, (b1[o] - mm1[o]) * s2);
        b1d[o] = b1[o];
    }
    // zero D pad rows (200..207) and init scores
    for (int i = tid; i < 8 * DROW; i += 256) Dsh[200 * DROW + i] = 0.0f;
    if (tid < 208) sc[tid] = (tid < 200) ? smf[O_SC0] : 0.0f;
    __syncthreads();

    // ===================== Phase B: layer0 + dice0 -> Dsh (tf32, slot layout) ===
    // 200 threads, 1 position each; f32x2 packs channel pair (chA, chB=chA+4),
    // whose outputs land at adjacent slots -> one STS.64 per pair.
    if (tid < 200) {
        const int t = tid;
        ull kd[12];
        #pragma unroll
        for (int i = 0; i < 12; ++i) {
            float kv = ksh[t * 12 + i];
            kd[i] = pack2(kv, kv);
        }
        float* drow = Dsh + t * DROW;
        #pragma unroll 2
        for (int bp = 0; bp < 40; ++bp) {
            ull acc = ((const ull*)Bfi)[bp];  // (base_chA, base_chB) via slot order
            const ulonglong2* mp = ((const ulonglong2*)Mp) + bp * 6;
            #pragma unroll
            for (int i2 = 0; i2 < 6; ++i2) {
                ulonglong2 m = mp[i2];
                ffma2(acc, kd[2 * i2],     m.x);
                ffma2(acc, kd[2 * i2 + 1], m.y);
            }
            float xA, xB;
            unpack2(acc, xA, xB);
            float dA = dice4(xA, d0c[2 * bp]);
            float dB = dice4(xB, d0c[2 * bp + 1]);
            // physical slot pair = (8*(bp>>2) + 2*(bp&3), +1)
            int pp = 8 * (bp >> 2) + 2 * (bp & 3);
            *(float2*)(drow + pp) = make_float2(
                __uint_as_float(cvt_tf32(dA)), __uint_as_float(cvt_tf32(dB)));
        }
    }
    __syncthreads();

    // ===================== Phase C: layer1 GEMM via tf32 HMMA + dice1 epilogue ==
    // h[208 x 40] = D[208 x 80] @ W1t[80 x 40]; 13 pos-tiles (16) x 5 j-tiles (8)
    {
        const int g  = lane & 3;   // k-col group
        const int rw = lane >> 2;  // row / n within fragment

        for (int item = wid; item < 65; item += 8) {
            const int pt = item % 13, jt = item / 13;
            const int pr = pt * 16, j0 = jt * 8;

            // B fragments: b0 = W1[kt*8+g][j0+rw], b1 = W1[kt*8+g+4][j0+rw]
            uint bf[10][2];
            #pragma unroll
            for (int kt = 0; kt < 10; ++kt) {
                int krow = kt * 8 + g;
                bf[kt][0] = __float_as_uint(W1t[krow * 40 + j0 + rw]);
                bf[kt][1] = __float_as_uint(W1t[(krow + 4) * 40 + j0 + rw]);
            }

            float e0 = 0.f, e1 = 0.f, e2 = 0.f, e3 = 0.f;  // even-kt acc
            float o0 = 0.f, o1 = 0.f, o2 = 0.f, o3 = 0.f;  // odd-kt acc
            const float* da = Dsh + (pr + rw) * DROW;
            const float* db = da + 8 * DROW;
            #pragma unroll
            for (int kt = 0; kt < 10; kt += 2) {
                int c0 = kt * 8 + 2 * g;   // slot of (a0,a2) pair
                float2 A02 = *(const float2*)(da + c0);  // (A[rw][k g], A[rw][g+4])
                float2 A13 = *(const float2*)(db + c0);  // rows +8
                mma16n8k8(e0, e1, e2, e3,
                          __float_as_uint(A02.x), __float_as_uint(A13.x),
                          __float_as_uint(A02.y), __float_as_uint(A13.y),
                          bf[kt][0], bf[kt][1]);
                float2 B02 = *(const float2*)(da + c0 + 8);
                float2 B13 = *(const float2*)(db + c0 + 8);
                mma16n8k8(o0, o1, o2, o3,
                          __float_as_uint(B02.x), __float_as_uint(B13.x),
                          __float_as_uint(B02.y), __float_as_uint(B13.y),
                          bf[kt + 1][0], bf[kt + 1][1]);
            }
            float c0 = e0 + o0, c1 = e1 + o1, c2 = e2 + o2, c3 = e3 + o3;
            // acc layout: c0=h[pr+rw][ja], c1=h[pr+rw][ja+1], c2=h[pr+rw+8][ja], c3=..[ja+1]
            const int ja = j0 + 2 * g;
            float4 ca = d1c[ja], cb = d1c[ja + 1];
            float  ba = b1d[ja], bb = b1d[ja + 1];
            // contribution = (c + b1) * fma(C2k, tanh(fma(c, S2, MS2')), A2k)
            float s0 = (c0 + ba) * fmaf(ca.y, tanhx(fmaf(c0, ca.z, ca.w)), ca.x)
                     + (c1 + bb) * fmaf(cb.y, tanhx(fmaf(c1, cb.z, cb.w)), cb.x);
            float s1 = (c2 + ba) * fmaf(ca.y, tanhx(fmaf(c2, ca.z, ca.w)), ca.x)
                     + (c3 + bb) * fmaf(cb.y, tanhx(fmaf(c3, cb.z, cb.w)), cb.x);
            // reduce over the 4 lanes sharing this row (xor 1, xor 2)
            s0 += __shfl_xor_sync(0xFFFFFFFF, s0, 1);
            s0 += __shfl_xor_sync(0xFFFFFFFF, s0, 2);
            s1 += __shfl_xor_sync(0xFFFFFFFF, s1, 1);
            s1 += __shfl_xor_sync(0xFFFFFFFF, s1, 2);
            if (g == 0) {
                atomicAdd(sc + pr + rw, s0);
                atomicAdd(sc + pr + rw + 8, s1);
            }
        }
    }
    __syncthreads();

    // ===================== Final: out[b][e] = sum_t sc[t] * keys[b][t][e] ======
    // (UNMASKED scores, reproducing the reference bug faithfully)
    if (tid < 96) {
        int e = tid % 12;
        int c = tid / 12;     // 8 chunks of 25 positions
        float acc = 0.0f;
        int t0 = c * 25;
        #pragma unroll 5
        for (int t2 = t0; t2 < t0 + 25; ++t2)
            acc = fmaf(sc[t2], ksh[t2 * 12 + e], acc);
        psum[tid] = acc;
    }
    __syncthreads();
    if (tid < 12) {
        float acc = 0.0f;
        #pragma unroll
        for (int c = 0; c < 8; ++c) acc += psum[c * 12 + tid];
        out[b * 12 + tid] = acc;
    }
}

extern "C" void kernel_launch(void* const* d_in, const int* in_sizes, int n_in,
                              void* d_out, int out_size) {
    const float* query  = (const float*)d_in[0];
    const float* keys   = (const float*)d_in[1];
    // d_in[2] = mask (bool) -- intentionally unused: reference overwrites the
    // masked scores and matmuls the UNMASKED scores (bug reproduced faithfully)
    const float* W0     = (const float*)d_in[3];
    const float* b0     = (const float*)d_in[4];
    const float* W1     = (const float*)d_in[5];
    const float* b1     = (const float*)d_in[6];
    const float* alpha0 = (const float*)d_in[7];
    const float* alpha1 = (const float*)d_in[8];
    const float* mm0    = (const float*)d_in[9];
    const float* mv0    = (const float*)d_in[10];
    const float* mm1    = (const float*)d_in[11];
    const float* mv1    = (const float*)d_in[12];
    const float* ak     = (const float*)d_in[13];
    const float* ab     = (const float*)d_in[14];
    float* out = (float*)d_out;

    // idempotent attribute set, not a stream op -> graph-capture safe
    cudaFuncSetAttribute(din_kernel, cudaFuncAttributeMaxDynamicSharedMemorySize,
                         SMEM_BYTES);

    int B = out_size / 12;  // [B, 1, 12]
    din_kernel<<<B, 256, SMEM_BYTES>>>(query, keys, W0, b0, W1, b1, alpha0, alpha1,
                                       mm0, mv0, mm1, mv1, ak, ab, out);
}

// round 7
// speedup vs baseline: 1.0662x; 1.0424x over previous
#include <cuda_runtime.h>

typedef unsigned long long ull;
typedef unsigned int uint;

__device__ __forceinline__ ull pack2(float lo, float hi) {
    ull v; asm("mov.b64 %0, {%1, %2};" : "=l"(v) : "f"(lo), "f"(hi)); return v;
}
__device__ __forceinline__ void unpack2(ull v, float& lo, float& hi) {
    asm("mov.b64 {%0, %1}, %2;" : "=f"(lo), "=f"(hi) : "l"(v));
}
__device__ __forceinline__ void ffma2(ull& d, ull a, ull b) {
    asm("fma.rn.f32x2 %0, %1, %2, %0;" : "+l"(d) : "l"(a), "l"(b));
}
__device__ __forceinline__ float tanhx(float x) {
    float y; asm("tanh.approx.f32 %0, %1;" : "=f"(y) : "f"(x)); return y;
}
__device__ __forceinline__ uint cvt_tf32(float x) {
    uint r; asm("cvt.rna.tf32.f32 %0, %1;" : "=r"(r) : "f"(x)); return r;
}
// Dice via tanh: dice(x) = x * fma(C2, tanh(fma(x, S2, MS2)), A2)
__device__ __forceinline__ float dice4(float x, float4 c) {
    return x * fmaf(c.y, tanhx(fmaf(x, c.z, c.w)), c.x);
}
// m16n8k8 tf32 warp MMA (A row-major, B col-major, fp32 accum)
__device__ __forceinline__ void mma16n8k8(float& d0, float& d1, float& d2, float& d3,
                                          uint a0, uint a1, uint a2, uint a3,
                                          uint b0, uint b1) {
    asm("mma.sync.aligned.m16n8k8.row.col.f32.tf32.tf32.f32 "
        "{%0,%1,%2,%3}, {%4,%5,%6,%7}, {%8,%9}, {%0,%1,%2,%3};"
        : "+f"(d0), "+f"(d1), "+f"(d2), "+f"(d3)
        : "r"(a0), "r"(a1), "r"(a2), "r"(a3), "r"(b0), "r"(b1));
}
// interleave within each 8-index block: slot(c) = (c&~7) + 2*(c&3) + ((c>>2)&1)
// => indices (8k+g, 8k+g+4) land at adjacent slots (8k+2g, 8k+2g+1)
__device__ __forceinline__ int slot_of(int c) {
    return (c & ~7) + 2 * (c & 3) + ((c >> 2) & 1);
}

// Shared memory layout (floats):
static constexpr int DROW   = 84;                 // D row stride (mult of 4 for STS.128)
static constexpr int WROW   = 82;                 // W1c row stride
static constexpr int O_DSH  = 0;                  // Dsh [208][84]            17472
static constexpr int O_KSH  = O_DSH + 208*DROW;   // ksh [200][13]            2600
static constexpr int O_W1C  = O_KSH + 2600;       // W1c [40][82] (k-slot)    3280
static constexpr int O_MP   = O_W1C + 40*WROW;    // Mp pair-packed           960
static constexpr int O_D0C  = O_MP + 960;         // d0c float4[80] slot ord  320
static constexpr int O_D1C  = O_D0C + 320;        // d1c float4[40]           160
static constexpr int O_BF   = O_D1C + 160;        // Bfi [80] slot order      80
static constexpr int O_B1D  = O_BF + 80;          // b1d [40]                 40
static constexpr int O_SC   = O_B1D + 40;         // sc [208]                 208
static constexpr int O_PSUM = O_SC + 208;         // psum [96]                96
static constexpr int O_QS   = O_PSUM + 96;        // qs [12]                  12
static constexpr int O_SC0  = O_QS + 12;          // score0 (+pad)            4
static constexpr int SMEM_FLOATS = O_SC0 + 4;
static constexpr int SMEM_BYTES  = SMEM_FLOATS * 4;   // ~100.9 KB -> 2 CTAs/SM

__global__ void __launch_bounds__(256, 2) din_kernel(
    const float* __restrict__ query, const float* __restrict__ keys,
    const float* __restrict__ W0, const float* __restrict__ b0,
    const float* __restrict__ W1, const float* __restrict__ b1,
    const float* __restrict__ alpha0, const float* __restrict__ alpha1,
    const float* __restrict__ mm0, const float* __restrict__ mv0,
    const float* __restrict__ mm1, const float* __restrict__ mv1,
    const float* __restrict__ ak, const float* __restrict__ ab,
    float* __restrict__ out)
{
    extern __shared__ __align__(16) float smf[];
    float*  Dsh  = smf + O_DSH;
    float*  ksh  = smf + O_KSH;      // stride 13 (conflict-free LDS)
    float*  W1c  = smf + O_W1C;      // W1c[j*82 + kslot] = tf32(W1[k][j])
    float*  Mp   = smf + O_MP;
    float4* d0c  = (float4*)(smf + O_D0C);
    float4* d1c  = (float4*)(smf + O_D1C);
    float*  Bfi  = smf + O_BF;
    float*  b1d  = smf + O_B1D;
    float*  sc   = smf + O_SC;
    float*  psum = smf + O_PSUM;
    float*  qs   = smf + O_QS;

    const int tid  = threadIdx.x;
    const int b    = blockIdx.x;
    const int wid  = tid >> 5;
    const int lane = tid & 31;
    const float EPS = 1e-9f;

    if (tid < 12) qs[tid] = query[b * 12 + tid];
    if (tid == 0) smf[O_SC0] = ab[0];
    __syncthreads();  // qs needed below

    // ===================== Phase A: cooperative precompute =====================
    // keys -> stride-13 shared layout
    for (int idx = tid; idx < 2400; idx += 256) {
        int t = idx / 12, e = idx % 12;
        ksh[t * 13 + e] = keys[(size_t)b * 2400 + idx];
    }
    // W1 -> transposed, k-slot interleaved, tf32-rounded
    for (int idx = tid; idx < 3200; idx += 256) {
        int k = idx / 40, j = idx % 40;
        W1c[j * WROW + slot_of(k)] = __uint_as_float(cvt_tf32(W1[idx]));
    }
    // Mp: pair-packed M. bp in [0,40): chA = 8*(bp>>2)+(bp&3), chB = chA+4.
    // float at Mp[bp*24 + 2i + half] = M[chA + 4*half][i]
    for (int idx = tid; idx < 960; idx += 256) {
        int bp = idx / 24, rem = idx % 24;
        int i = rem >> 1, half = rem & 1;
        int ch = 8 * (bp >> 2) + (bp & 3) + 4 * half;
        Mp[idx] = W0[(12 + i) * 80 + ch] - W0[(24 + i) * 80 + ch]
                + qs[i] * W0[(36 + i) * 80 + ch];
    }
    // base + dice0 constants in slot order
    if (tid < 80) {
        int o = tid;
        float s = b0[o];
        #pragma unroll
        for (int i = 0; i < 12; ++i)
            s += qs[i] * (W0[i * 80 + o] + W0[(24 + i) * 80 + o]);
        int sl = slot_of(o);
        Bfi[sl] = s;
        float a  = alpha0[o];
        float c2 = 0.5f * (1.0f - a);
        float s2 = 0.5f * rsqrtf(mv0[o] + EPS);
        d0c[sl] = make_float4(a + c2, c2, s2, -mm0[o] * s2);
    }
    // dice1 constants with ak folded; MS2' absorbs b1 shift (z uses raw acc c)
    if (tid < 40) {
        int o = tid;
        float a  = alpha1[o];
        float kk = ak[o];
        float c2 = 0.5f * (1.0f - a);
        float s2 = 0.5f * rsqrtf(mv1[o] + EPS);
        d1c[o] = make_float4((a + c2) * kk, c2 * kk, s2, (b1[o] - mm1[o]) * s2);
        b1d[o] = b1[o];
    }
    // zero D pad rows (200..207)
    for (int i = tid; i < 8 * DROW; i += 256) Dsh[200 * DROW + i] = 0.0f;
    __syncthreads();

    // ===================== Phase B: layer0 + dice0 -> Dsh (tf32, slot layout) ===
    // 200 threads, 1 position each; bp processed in PAIRS -> 2 independent
    // FFMA2 chains + one STS.128 per pair (slots 4*bp2 .. 4*bp2+3 contiguous).
    if (tid < 200) {
        const int t = tid;
        ull kd[12];
        #pragma unroll
        for (int i = 0; i < 12; ++i) {
            float kv = ksh[t * 13 + i];
            kd[i] = pack2(kv, kv);
        }
        float* drow = Dsh + t * DROW;
        #pragma unroll 2
        for (int bp2 = 0; bp2 < 20; ++bp2) {
            // bases for bp=2*bp2 and bp+1: slots 4*bp2 .. 4*bp2+3
            ulonglong2 BV = *(const ulonglong2*)(Bfi + 4 * bp2);
            ull acc0 = BV.x;   // (xA of bp,   xB of bp)
            ull acc1 = BV.y;   // (xA of bp+1, xB of bp+1)
            const ulonglong2* mpA = (const ulonglong2*)(Mp + 48 * bp2);
            const ulonglong2* mpB = mpA + 6;  // bp+1's block: +24 floats = +6 u64x2
            #pragma unroll
            for (int i2 = 0; i2 < 6; ++i2) {
                ulonglong2 ma = mpA[i2];
                ulonglong2 mb = mpB[i2];
                ffma2(acc0, kd[2 * i2],     ma.x);
                ffma2(acc1, kd[2 * i2],     mb.x);
                ffma2(acc0, kd[2 * i2 + 1], ma.y);
                ffma2(acc1, kd[2 * i2 + 1], mb.y);
            }
            float x0, x1, x2, x3;
            unpack2(acc0, x0, x1);
            unpack2(acc1, x2, x3);
            int cbase = 4 * bp2;
            float d0v = dice4(x0, d0c[cbase]);
            float d1v = dice4(x1, d0c[cbase + 1]);
            float d2v = dice4(x2, d0c[cbase + 2]);
            float d3v = dice4(x3, d0c[cbase + 3]);
            float4 o4 = make_float4(
                __uint_as_float(cvt_tf32(d0v)), __uint_as_float(cvt_tf32(d1v)),
                __uint_as_float(cvt_tf32(d2v)), __uint_as_float(cvt_tf32(d3v)));
            *(float4*)(drow + cbase) = o4;
        }
    }
    __syncthreads();

    // ===================== Phase C: layer1 GEMM, A cached in registers ==========
    // h[208 x 40] = D[208 x 80] @ W1[80 x 40]. Warp owns pos-tile(s) of 16 rows:
    // loads its 40 A-regs ONCE, runs all 5 j-tiles (50 HMMA) against them.
    {
        const int g  = lane & 3;   // k-col group
        const int rw = lane >> 2;  // row within fragment
        const float score0 = smf[O_SC0];

        for (int pt = wid; pt < 13; pt += 8) {
            const int pr = pt * 16;
            const float* da = Dsh + (pr + rw) * DROW;
            const float* db = da + 8 * DROW;
            // A fragments, 10 k-tiles x 4 regs (slot layout -> LDS.64 pairs)
            uint af[10][4];
            #pragma unroll
            for (int kt = 0; kt < 10; ++kt) {
                float2 x = *(const float2*)(da + 8 * kt + 2 * g);
                float2 y = *(const float2*)(db + 8 * kt + 2 * g);
                af[kt][0] = __float_as_uint(x.x);
                af[kt][1] = __float_as_uint(y.x);
                af[kt][2] = __float_as_uint(x.y);
                af[kt][3] = __float_as_uint(y.y);
            }
            float acc[5][4];
            #pragma unroll
            for (int jt = 0; jt < 5; ++jt)
                acc[jt][0] = acc[jt][1] = acc[jt][2] = acc[jt][3] = 0.0f;

            const float* wbase = W1c + rw * WROW + 2 * g;
            #pragma unroll
            for (int kt = 0; kt < 10; ++kt) {
                const float* wk = wbase + 8 * kt;
                #pragma unroll
                for (int jt = 0; jt < 5; ++jt) {
                    // (b0,b1) = W1[kt*8+g][jt*8+rw], W1[kt*8+g+4][jt*8+rw]
                    float2 bw = *(const float2*)(wk + jt * 8 * WROW);
                    mma16n8k8(acc[jt][0], acc[jt][1], acc[jt][2], acc[jt][3],
                              af[kt][0], af[kt][1], af[kt][2], af[kt][3],
                              __float_as_uint(bw.x), __float_as_uint(bw.y));
                }
            }
            // epilogue: dice1(+ak folded) per jt, accumulate row sums in regs
            float r0 = 0.0f, r1 = 0.0f;
            #pragma unroll
            for (int jt = 0; jt < 5; ++jt) {
                const int ja = jt * 8 + 2 * g;
                float4 ca = d1c[ja], cb = d1c[ja + 1];
                float  ba = b1d[ja], bb = b1d[ja + 1];
                float c0 = acc[jt][0], c1 = acc[jt][1];
                float c2 = acc[jt][2], c3 = acc[jt][3];
                r0 += (c0 + ba) * fmaf(ca.y, tanhx(fmaf(c0, ca.z, ca.w)), ca.x)
                    + (c1 + bb) * fmaf(cb.y, tanhx(fmaf(c1, cb.z, cb.w)), cb.x);
                r1 += (c2 + ba) * fmaf(ca.y, tanhx(fmaf(c2, ca.z, ca.w)), ca.x)
                    + (c3 + bb) * fmaf(cb.y, tanhx(fmaf(c3, cb.z, cb.w)), cb.x);
            }
            // reduce over the 4 lanes (g) sharing each row; rows are warp-exclusive
            r0 += __shfl_xor_sync(0xFFFFFFFF, r0, 1);
            r0 += __shfl_xor_sync(0xFFFFFFFF, r0, 2);
            r1 += __shfl_xor_sync(0xFFFFFFFF, r1, 1);
            r1 += __shfl_xor_sync(0xFFFFFFFF, r1, 2);
            if (g == 0) {
                sc[pr + rw]     = score0 + r0;
                sc[pr + rw + 8] = score0 + r1;
            }
        }
    }
    __syncthreads();

    // ===================== Final: out[b][e] = sum_t sc[t] * keys[b][t][e] ======
    // (UNMASKED scores, reproducing the reference bug faithfully)
    if (tid < 96) {
        int e = tid % 12;
        int c = tid / 12;     // 8 chunks of 25 positions
        float acc = 0.0f;
        int t0 = c * 25;
        #pragma unroll 5
        for (int t2 = t0; t2 < t0 + 25; ++t2)
            acc = fmaf(sc[t2], ksh[t2 * 13 + e], acc);
        psum[tid] = acc;
    }
    __syncthreads();
    if (tid < 12) {
        float acc = 0.0f;
        #pragma unroll
        for (int c = 0; c < 8; ++c) acc += psum[c * 12 + tid];
        out[b * 12 + tid] = acc;
    }
}

extern "C" void kernel_launch(void* const* d_in, const int* in_sizes, int n_in,
                              void* d_out, int out_size) {
    const float* query  = (const float*)d_in[0];
    const float* keys   = (const float*)d_in[1];
    // d_in[2] = mask (bool) -- intentionally unused: reference overwrites the
    // masked scores and matmuls the UNMASKED scores (bug reproduced faithfully)
    const float* W0     = (const float*)d_in[3];
    const float* b0     = (const float*)d_in[4];
    const float* W1     = (const float*)d_in[5];
    const float* b1     = (const float*)d_in[6];
    const float* alpha0 = (const float*)d_in[7];
    const float* alpha1 = (const float*)d_in[8];
    const float* mm0    = (const float*)d_in[9];
    const float* mv0    = (const float*)d_in[10];
    const float* mm1    = (const float*)d_in[11];
    const float* mv1    = (const float*)d_in[12];
    const float* ak     = (const float*)d_in[13];
    const float* ab     = (const float*)d_in[14];
    float* out = (float*)d_out;

    // idempotent attribute set, not a stream op -> graph-capture safe
    cudaFuncSetAttribute(din_kernel, cudaFuncAttributeMaxDynamicSharedMemorySize,
                         SMEM_BYTES);

    int B = out_size / 12;  // [B, 1, 12]
    din_kernel<<<B, 256, SMEM_BYTES>>>(query, keys, W0, b0, W1, b1, alpha0, alpha1,
                                       mm0, mv0, mm1, mv1, ak, ab, out);
}

// round 8
// speedup vs baseline: 1.5832x; 1.4849x over previous
#include <cuda_runtime.h>

typedef unsigned long long ull;
typedef unsigned int uint;

__device__ __forceinline__ float tanhx(float x) {
    float y; asm("tanh.approx.f32 %0, %1;" : "=f"(y) : "f"(x)); return y;
}
__device__ __forceinline__ uint cvt_tf32(float x) {
    uint r; asm("cvt.rna.tf32.f32 %0, %1;" : "=r"(r) : "f"(x)); return r;
}
// Dice via tanh: dice(x) = x * fma(C2, tanh(fma(x, S2, MS2)), A2)
__device__ __forceinline__ float dice4(float x, float4 c) {
    return x * fmaf(c.y, tanhx(fmaf(x, c.z, c.w)), c.x);
}
// m16n8k8 tf32 warp MMA (A row-major, B col-major, fp32 accum)
__device__ __forceinline__ void mma16n8k8(float& d0, float& d1, float& d2, float& d3,
                                          uint a0, uint a1, uint a2, uint a3,
                                          uint b0, uint b1) {
    asm("mma.sync.aligned.m16n8k8.row.col.f32.tf32.tf32.f32 "
        "{%0,%1,%2,%3}, {%4,%5,%6,%7}, {%8,%9}, {%0,%1,%2,%3};"
        : "+f"(d0), "+f"(d1), "+f"(d2), "+f"(d3)
        : "r"(a0), "r"(a1), "r"(a2), "r"(a3), "r"(b0), "r"(b1));
}
// k-slot interleave within each 8-index block: (8m+g, 8m+g+4) -> (8m+2g, 8m+2g+1)
__device__ __forceinline__ int slot_of(int c) {
    return (c & ~7) + 2 * (c & 3) + ((c >> 2) & 1);
}

// Shared memory layout (floats):
static constexpr int DROW   = 84;                 // Dsh row stride (natural ch order)
static constexpr int WROW   = 88;                 // W1c row stride (conflict-free LDS.64)
static constexpr int MROW   = 24;                 // Mtc row stride (conflict-free LDS.64)
static constexpr int O_DSH  = 0;                  // Dsh [208][84]         17472
static constexpr int O_KSH  = O_DSH + 208*DROW;   // ksh [208][12]         2496
static constexpr int O_W1C  = O_KSH + 2496;       // W1c [40][88] k-slot   3520
static constexpr int O_MTC  = O_W1C + 40*WROW;    // Mtc [80][24] k-slot   1920
static constexpr int O_D0C  = O_MTC + 80*MROW;    // d0c float4[80]        320
static constexpr int O_D1C  = O_D0C + 320;        // d1c float4[40]        160
static constexpr int O_B1D  = O_D1C + 160;        // b1d [40]              40
static constexpr int O_SC   = O_B1D + 40;         // sc [208]              208
static constexpr int O_PSUM = O_SC + 208;         // psum [96]             96
static constexpr int O_QS   = O_PSUM + 96;        // qs [12]               12
static constexpr int O_SC0  = O_QS + 12;          // score0 (+pad)         4
static constexpr int SMEM_FLOATS = O_SC0 + 4;
static constexpr int SMEM_BYTES  = SMEM_FLOATS * 4;   // ~102.5 KB -> 2 CTAs/SM

__global__ void __launch_bounds__(256, 2) din_kernel(
    const float* __restrict__ query, const float* __restrict__ keys,
    const float* __restrict__ W0, const float* __restrict__ b0,
    const float* __restrict__ W1, const float* __restrict__ b1,
    const float* __restrict__ alpha0, const float* __restrict__ alpha1,
    const float* __restrict__ mm0, const float* __restrict__ mv0,
    const float* __restrict__ mm1, const float* __restrict__ mv1,
    const float* __restrict__ ak, const float* __restrict__ ab,
    float* __restrict__ out)
{
    extern __shared__ __align__(16) float smf[];
    float*  Dsh  = smf + O_DSH;      // layer-0 diced output, tf32 bits, natural ch order
    float*  ksh  = smf + O_KSH;      // keys natural [208][12], rows 200-207 zero
    float*  W1c  = smf + O_W1C;      // W1c[j*88 + slot(k)] = tf32(W1[k][j])
    float*  Mtc  = smf + O_MTC;      // Mtc[o*24 + slot(k)] = tf32(M[k][o]); row12=base
    float4* d0c  = (float4*)(smf + O_D0C);   // natural channel order
    float4* d1c  = (float4*)(smf + O_D1C);
    float*  b1d  = smf + O_B1D;
    float*  sc   = smf + O_SC;
    float*  psum = smf + O_PSUM;
    float*  qs   = smf + O_QS;

    const int tid  = threadIdx.x;
    const int b    = blockIdx.x;
    const int wid  = tid >> 5;
    const int lane = tid & 31;
    const int g    = lane & 3;    // k-col group
    const int rw   = lane >> 2;   // row within fragment
    const float EPS = 1e-9f;

    if (tid < 12) qs[tid] = query[b * 12 + tid];
    if (tid == 0) smf[O_SC0] = ab[0];
    __syncthreads();  // qs needed by Mtc fill

    // ===================== Phase A: cooperative precompute =====================
    // keys: natural layout, float4 copy; zero pad rows 200..207
    {
        const float4* gk = (const float4*)(keys + (size_t)b * 2400);
        float4* sk = (float4*)ksh;
        for (int i = tid; i < 600; i += 256) sk[i] = gk[i];
        if (tid < 96) ksh[2400 + tid] = 0.0f;
    }
    // W1 -> transposed, k-slot interleaved, tf32 (200 threads, cheap indexing)
    if (tid < 200) {
        int j = tid % 40, k0 = tid / 40;
        #pragma unroll
        for (int it = 0; it < 16; ++it) {
            int k = k0 + 5 * it;
            W1c[j * WROW + slot_of(k)] = __uint_as_float(cvt_tf32(W1[k * 40 + j]));
        }
    }
    // Mtc rows 0..11: M[k][o] = W0[12+k][o] - W0[24+k][o] + q_k * W0[36+k][o]
    // + zero rows 13..15 (slots 11,13,15)
    if (tid < 240) {
        int o = tid % 80, kg = tid / 80;
        #pragma unroll
        for (int kk = 0; kk < 4; ++kk) {
            int k = kg * 4 + kk;
            float m = W0[(12 + k) * 80 + o] - W0[(24 + k) * 80 + o]
                    + qs[k] * W0[(36 + k) * 80 + o];
            Mtc[o * MROW + slot_of(k)] = __uint_as_float(cvt_tf32(m));
        }
        Mtc[o * MROW + 11 + 2 * kg] = 0.0f;   // slots 11,13,15
    }
    // Mtc row 12 (slot 9) = base[o]; paired with the K ones-column. Also d0c.
    if (tid < 80) {
        int o = tid;
        float s = b0[o];
        #pragma unroll
        for (int i = 0; i < 12; ++i)
            s += qs[i] * (W0[i * 80 + o] + W0[(24 + i) * 80 + o]);
        Mtc[o * MROW + 9] = __uint_as_float(cvt_tf32(s));
        float a  = alpha0[o];
        float c2 = 0.5f * (1.0f - a);
        float s2 = 0.5f * rsqrtf(mv0[o] + EPS);
        d0c[o] = make_float4(a + c2, c2, s2, -mm0[o] * s2);
    }
    // dice1 constants with ak folded; MS2' absorbs b1 shift (z uses raw acc c)
    if (tid < 40) {
        int o = tid;
        float a  = alpha1[o];
        float kk = ak[o];
        float c2 = 0.5f * (1.0f - a);
        float s2 = 0.5f * rsqrtf(mv1[o] + EPS);
        d1c[o] = make_float4((a + c2) * kk, c2 * kk, s2, (b1[o] - mm1[o]) * s2);
        b1d[o] = b1[o];
    }
    __syncthreads();

    // ============ Phase B: layer0 as tf32 HMMA (+bias ones-column) + dice0 =====
    // D0[208x80] = K[208x16] @ M[16x80]; per warp per 16-pos tile: 20 HMMA.
    for (int pt = wid; pt < 13; pt += 8) {
        const int r0 = pt * 16 + rw, r1 = r0 + 8;
        const float* k0p = ksh + r0 * 12;
        const float* k1p = ksh + r1 * 12;
        // kt=0 A-frag: k-cols g, g+4
        uint ka0 = cvt_tf32(k0p[g]),     ka1 = cvt_tf32(k1p[g]);
        uint ka2 = cvt_tf32(k0p[g + 4]), ka3 = cvt_tf32(k1p[g + 4]);
        // kt=1 A-frag: k-cols 8+g (valid) and 12+g (ones column for g==0, else 0)
        uint kb0 = cvt_tf32(k0p[8 + g]), kb1 = cvt_tf32(k1p[8 + g]);
        uint one = (g == 0) ? 0x3F800000u : 0u;

        float acc[10][4];
        #pragma unroll
        for (int jt = 0; jt < 10; ++jt)
            acc[jt][0] = acc[jt][1] = acc[jt][2] = acc[jt][3] = 0.0f;

        #pragma unroll
        for (int jt = 0; jt < 10; ++jt) {
            const float* mrow = Mtc + (jt * 8 + rw) * MROW + 2 * g;
            float2 w0 = *(const float2*)(mrow);       // (M[g][o],   M[g+4][o])
            float2 w1 = *(const float2*)(mrow + 8);   // (M[8+g][o], M[12+g][o])
            mma16n8k8(acc[jt][0], acc[jt][1], acc[jt][2], acc[jt][3],
                      ka0, ka1, ka2, ka3,
                      __float_as_uint(w0.x), __float_as_uint(w0.y));
            mma16n8k8(acc[jt][0], acc[jt][1], acc[jt][2], acc[jt][3],
                      kb0, kb1, one, one,
                      __float_as_uint(w1.x), __float_as_uint(w1.y));
        }
        // dice0 + tf32 + store (natural channel order, STS.64 pairs)
        float* d0 = Dsh + r0 * DROW;
        float* d1 = Dsh + r1 * DROW;
        #pragma unroll
        for (int jt = 0; jt < 10; ++jt) {
            const int ja = jt * 8 + 2 * g;
            float4 ca = d0c[ja], cb = d0c[ja + 1];
            float v00 = dice4(acc[jt][0], ca);   // (r0, ja)
            float v01 = dice4(acc[jt][1], cb);   // (r0, ja+1)
            float v10 = dice4(acc[jt][2], ca);   // (r1, ja)
            float v11 = dice4(acc[jt][3], cb);   // (r1, ja+1)
            *(float2*)(d0 + ja) = make_float2(
                __uint_as_float(cvt_tf32(v00)), __uint_as_float(cvt_tf32(v01)));
            *(float2*)(d1 + ja) = make_float2(
                __uint_as_float(cvt_tf32(v10)), __uint_as_float(cvt_tf32(v11)));
        }
    }
    __syncthreads();

    // ===================== Phase C: layer1 GEMM, A cached in registers ==========
    // h[208x40] = D[208x80] @ W1[80x40]; warp owns pos-tile(s), A loaded once.
    {
        const float score0 = smf[O_SC0];
        for (int pt = wid; pt < 13; pt += 8) {
            const int pr = pt * 16;
            const float* da = Dsh + (pr + rw) * DROW;
            const float* db = da + 8 * DROW;
            uint af[10][4];
            #pragma unroll
            for (int kt = 0; kt < 10; ++kt) {
                af[kt][0] = __float_as_uint(da[8 * kt + g]);
                af[kt][1] = __float_as_uint(db[8 * kt + g]);
                af[kt][2] = __float_as_uint(da[8 * kt + g + 4]);
                af[kt][3] = __float_as_uint(db[8 * kt + g + 4]);
            }
            float acc[5][4];
            #pragma unroll
            for (int jt = 0; jt < 5; ++jt)
                acc[jt][0] = acc[jt][1] = acc[jt][2] = acc[jt][3] = 0.0f;

            const float* wbase = W1c + rw * WROW + 2 * g;
            #pragma unroll
            for (int kt = 0; kt < 10; ++kt) {
                const float* wk = wbase + 8 * kt;
                #pragma unroll
                for (int jt = 0; jt < 5; ++jt) {
                    // (b0,b1) = W1[kt*8+g][jt*8+rw], W1[kt*8+g+4][jt*8+rw]
                    float2 bw = *(const float2*)(wk + jt * 8 * WROW);
                    mma16n8k8(acc[jt][0], acc[jt][1], acc[jt][2], acc[jt][3],
                              af[kt][0], af[kt][1], af[kt][2], af[kt][3],
                              __float_as_uint(bw.x), __float_as_uint(bw.y));
                }
            }
            // epilogue: dice1(+ak folded) per jt, accumulate row sums in regs
            float r0 = 0.0f, r1 = 0.0f;
            #pragma unroll
            for (int jt = 0; jt < 5; ++jt) {
                const int ja = jt * 8 + 2 * g;
                float4 ca = d1c[ja], cb = d1c[ja + 1];
                float  ba = b1d[ja], bb = b1d[ja + 1];
                float c0 = acc[jt][0], c1 = acc[jt][1];
                float c2 = acc[jt][2], c3 = acc[jt][3];
                r0 += (c0 + ba) * fmaf(ca.y, tanhx(fmaf(c0, ca.z, ca.w)), ca.x)
                    + (c1 + bb) * fmaf(cb.y, tanhx(fmaf(c1, cb.z, cb.w)), cb.x);
                r1 += (c2 + ba) * fmaf(ca.y, tanhx(fmaf(c2, ca.z, ca.w)), ca.x)
                    + (c3 + bb) * fmaf(cb.y, tanhx(fmaf(c3, cb.z, cb.w)), cb.x);
            }
            // reduce over the 4 lanes (g) sharing each row; rows warp-exclusive
            r0 += __shfl_xor_sync(0xFFFFFFFF, r0, 1);
            r0 += __shfl_xor_sync(0xFFFFFFFF, r0, 2);
            r1 += __shfl_xor_sync(0xFFFFFFFF, r1, 1);
            r1 += __shfl_xor_sync(0xFFFFFFFF, r1, 2);
            if (g == 0) {
                sc[pr + rw]     = score0 + r0;
                sc[pr + rw + 8] = score0 + r1;
            }
        }
    }
    __syncthreads();

    // ===================== Final: out[b][e] = sum_t sc[t] * keys[b][t][e] ======
    // (UNMASKED scores, reproducing the reference bug faithfully)
    if (tid < 96) {
        int e = tid % 12;
        int c = tid / 12;     // 8 chunks of 25 positions
        float acc = 0.0f;
        int t0 = c * 25;
        #pragma unroll 5
        for (int t2 = t0; t2 < t0 + 25; ++t2)
            acc = fmaf(sc[t2], ksh[t2 * 12 + e], acc);
        psum[tid] = acc;
    }
    __syncthreads();
    if (tid < 12) {
        float acc = 0.0f;
        #pragma unroll
        for (int c = 0; c < 8; ++c) acc += psum[c * 12 + tid];
        out[b * 12 + tid] = acc;
    }
}

extern "C" void kernel_launch(void* const* d_in, const int* in_sizes, int n_in,
                              void* d_out, int out_size) {
    const float* query  = (const float*)d_in[0];
    const float* keys   = (const float*)d_in[1];
    // d_in[2] = mask (bool) -- intentionally unused: reference overwrites the
    // masked scores and matmuls the UNMASKED scores (bug reproduced faithfully)
    const float* W0     = (const float*)d_in[3];
    const float* b0     = (const float*)d_in[4];
    const float* W1     = (const float*)d_in[5];
    const float* b1     = (const float*)d_in[6];
    const float* alpha0 = (const float*)d_in[7];
    const float* alpha1 = (const float*)d_in[8];
    const float* mm0    = (const float*)d_in[9];
    const float* mv0    = (const float*)d_in[10];
    const float* mm1    = (const float*)d_in[11];
    const float* mv1    = (const float*)d_in[12];
    const float* ak     = (const float*)d_in[13];
    const float* ab     = (const float*)d_in[14];
    float* out = (float*)d_out;

    // idempotent attribute set, not a stream op -> graph-capture safe
    cudaFuncSetAttribute(din_kernel, cudaFuncAttributeMaxDynamicSharedMemorySize,
                         SMEM_BYTES);

    int B = out_size / 12;  // [B, 1, 12]
    din_kernel<<<B, 256, SMEM_BYTES>>>(query, keys, W0, b0, W1, b1, alpha0, alpha1,
                                       mm0, mv0, mm1, mv1, ak, ab, out);
}

// round 9
// speedup vs baseline: 2.1595x; 1.3640x over previous
#include <cuda_runtime.h>

typedef unsigned int uint;

__device__ __forceinline__ float tanhx(float x) {
    float y; asm("tanh.approx.f32 %0, %1;" : "=f"(y) : "f"(x)); return y;
}
__device__ __forceinline__ uint cvt_tf32(float x) {
    uint r; asm("cvt.rna.tf32.f32 %0, %1;" : "=r"(r) : "f"(x)); return r;
}
// Dice via tanh: dice(x) = x * fma(C2, tanh(fma(x, S2, MS2)), A2)
__device__ __forceinline__ float dice4(float x, float4 c) {
    return x * fmaf(c.y, tanhx(fmaf(x, c.z, c.w)), c.x);
}
// m16n8k8 tf32 warp MMA (A row-major, B col-major, fp32 accum)
__device__ __forceinline__ void mma16n8k8(float& d0, float& d1, float& d2, float& d3,
                                          uint a0, uint a1, uint a2, uint a3,
                                          uint b0, uint b1) {
    asm("mma.sync.aligned.m16n8k8.row.col.f32.tf32.tf32.f32 "
        "{%0,%1,%2,%3}, {%4,%5,%6,%7}, {%8,%9}, {%0,%1,%2,%3};"
        : "+f"(d0), "+f"(d1), "+f"(d2), "+f"(d3)
        : "r"(a0), "r"(a1), "r"(a2), "r"(a3), "r"(b0), "r"(b1));
}
// k-slot interleave within each 8-index block: (8m+g, 8m+g+4) -> (8m+2g, 8m+2g+1)
__device__ __forceinline__ int slot_of(int c) {
    return (c & ~7) + 2 * (c & 3) + ((c >> 2) & 1);
}

static constexpr int NT     = 224;                // 7 warps
static constexpr int DROW   = 84;                 // slab row stride
static constexpr int SLAB   = 16 * DROW;          // 1344 floats per warp
static constexpr int WROW   = 84;                 // W1c row stride
static constexpr int MROW   = 24;                 // Mtc row stride
// Shared layout (floats):
static constexpr int O_SLAB = 0;                  // 7 * 1344 = 9408
static constexpr int O_KSH  = O_SLAB + 7*SLAB;    // ksh [208][12]       2496
static constexpr int O_W1C  = O_KSH + 2496;       // W1c [40][84]        3360
static constexpr int O_MTC  = O_W1C + 40*WROW;    // Mtc [80][24]        1920
static constexpr int O_D0C  = O_MTC + 80*MROW;    // d0c float4[80]      320
static constexpr int O_D1C  = O_D0C + 320;        // d1c float4[40]      160
static constexpr int O_B1D  = O_D1C + 160;        // b1d [40]            40
static constexpr int O_SC   = O_B1D + 40;         // sc [208]            208
static constexpr int O_PSUM = O_SC + 208;         // psum [96]           96
static constexpr int O_QS   = O_PSUM + 96;        // qs [12]             12
static constexpr int O_SC0  = O_QS + 12;          // score0 (+pad)       4
static constexpr int SMEM_FLOATS = O_SC0 + 4;     // 18024
static constexpr int SMEM_BYTES  = SMEM_FLOATS * 4;   // 72096 B -> 3 CTAs/SM

__global__ void __launch_bounds__(NT, 3) din_kernel(
    const float* __restrict__ query, const float* __restrict__ keys,
    const float* __restrict__ W0, const float* __restrict__ b0,
    const float* __restrict__ W1, const float* __restrict__ b1,
    const float* __restrict__ alpha0, const float* __restrict__ alpha1,
    const float* __restrict__ mm0, const float* __restrict__ mv0,
    const float* __restrict__ mm1, const float* __restrict__ mv1,
    const float* __restrict__ ak, const float* __restrict__ ab,
    float* __restrict__ out)
{
    extern __shared__ __align__(16) float smf[];
    float*  ksh  = smf + O_KSH;      // keys natural [208][12], rows 200-207 zero
    float*  W1c  = smf + O_W1C;      // W1c[j*84 + slot(k)] = tf32(W1[k][j])
    float*  Mtc  = smf + O_MTC;      // Mtc[o*24 + slot(k)] = tf32(M[k][o]); row12=base
    float4* d0c  = (float4*)(smf + O_D0C);
    float4* d1c  = (float4*)(smf + O_D1C);
    float*  b1d  = smf + O_B1D;
    float*  sc   = smf + O_SC;
    float*  psum = smf + O_PSUM;
    float*  qs   = smf + O_QS;

    const int tid  = threadIdx.x;
    const int b    = blockIdx.x;
    const int wid  = tid >> 5;
    const int lane = tid & 31;
    const int g    = lane & 3;    // k-col group
    const int rw   = lane >> 2;   // row within fragment
    const float EPS = 1e-9f;

    if (tid < 12) qs[tid] = query[b * 12 + tid];
    if (tid == 0) smf[O_SC0] = ab[0];
    __syncthreads();  // qs needed by Mtc fill

    // ===================== Phase A: cooperative precompute =====================
    // keys: natural layout, float4 copy; zero pad rows 200..207
    {
        const float4* gk = (const float4*)(keys + (size_t)b * 2400);
        float4* sk = (float4*)ksh;
        for (int i = tid; i < 600; i += NT) sk[i] = gk[i];
        if (tid < 96) ksh[2400 + tid] = 0.0f;
    }
    // W1 -> transposed, k-slot interleaved, tf32 (200 threads)
    if (tid < 200) {
        int j = tid % 40, k0 = tid / 40;
        #pragma unroll
        for (int it = 0; it < 16; ++it) {
            int k = k0 + 5 * it;
            W1c[j * WROW + slot_of(k)] = __uint_as_float(cvt_tf32(W1[k * 40 + j]));
        }
    }
    // Mtc rows 0..11: M[k][o] = W0[12+k][o] - W0[24+k][o] + q_k * W0[36+k][o]
    if (tid < 160) {
        int o = tid % 80, kg = tid / 80;
        #pragma unroll
        for (int kk = 0; kk < 6; ++kk) {
            int k = kg * 6 + kk;
            float m = W0[(12 + k) * 80 + o] - W0[(24 + k) * 80 + o]
                    + qs[k] * W0[(36 + k) * 80 + o];
            Mtc[o * MROW + slot_of(k)] = __uint_as_float(cvt_tf32(m));
        }
    }
    // Mtc row 12 (slot 9) = base[o]; zero rows 13..15 (slots 11,13,15); d0c.
    if (tid < 80) {
        int o = tid;
        float s = b0[o];
        #pragma unroll
        for (int i = 0; i < 12; ++i)
            s += qs[i] * (W0[i * 80 + o] + W0[(24 + i) * 80 + o]);
        Mtc[o * MROW + 9]  = __uint_as_float(cvt_tf32(s));
        Mtc[o * MROW + 11] = 0.0f;
        Mtc[o * MROW + 13] = 0.0f;
        Mtc[o * MROW + 15] = 0.0f;
        float a  = alpha0[o];
        float c2 = 0.5f * (1.0f - a);
        float s2 = 0.5f * rsqrtf(mv0[o] + EPS);
        d0c[o] = make_float4(a + c2, c2, s2, -mm0[o] * s2);
    }
    // dice1 constants with ak folded; MS2' absorbs b1 shift (z uses raw acc c)
    if (tid < 40) {
        int o = tid;
        float a  = alpha1[o];
        float kk = ak[o];
        float c2 = 0.5f * (1.0f - a);
        float s2 = 0.5f * rsqrtf(mv1[o] + EPS);
        d1c[o] = make_float4((a + c2) * kk, c2 * kk, s2, (b1[o] - mm1[o]) * s2);
        b1d[o] = b1[o];
    }
    __syncthreads();

    // ============ Fused per-tile: layer0 HMMA + dice0 -> slab -> layer1 HMMA ===
    // Per-warp private slab (16 rows x 84); no CTA-wide sync inside the loop.
    {
        float* slab = smf + O_SLAB + wid * SLAB;
        const float score0 = smf[O_SC0];

        for (int pt = wid; pt < 13; pt += 7) {
            const int r0 = pt * 16 + rw, r1 = r0 + 8;
            // ---- layer 0: D0[16x80] = K[16x16] @ M[16x80] (bias ones-column) ----
            const float* k0p = ksh + r0 * 12;
            const float* k1p = ksh + r1 * 12;
            uint ka0 = cvt_tf32(k0p[g]),     ka1 = cvt_tf32(k1p[g]);
            uint ka2 = cvt_tf32(k0p[g + 4]), ka3 = cvt_tf32(k1p[g + 4]);
            uint kb0 = cvt_tf32(k0p[8 + g]), kb1 = cvt_tf32(k1p[8 + g]);
            uint one = (g == 0) ? 0x3F800000u : 0u;

            float acc[10][4];
            #pragma unroll
            for (int jt = 0; jt < 10; ++jt)
                acc[jt][0] = acc[jt][1] = acc[jt][2] = acc[jt][3] = 0.0f;

            #pragma unroll
            for (int jt = 0; jt < 10; ++jt) {
                const float* mrow = Mtc + (jt * 8 + rw) * MROW + 2 * g;
                float2 w0 = *(const float2*)(mrow);       // (M[g][o],   M[g+4][o])
                float2 w1 = *(const float2*)(mrow + 8);   // (M[8+g][o], M[12+g][o])
                mma16n8k8(acc[jt][0], acc[jt][1], acc[jt][2], acc[jt][3],
                          ka0, ka1, ka2, ka3,
                          __float_as_uint(w0.x), __float_as_uint(w0.y));
                mma16n8k8(acc[jt][0], acc[jt][1], acc[jt][2], acc[jt][3],
                          kb0, kb1, one, one,
                          __float_as_uint(w1.x), __float_as_uint(w1.y));
            }
            // dice0 + tf32 -> slab rows rw, rw+8 (natural channel order)
            float* d0 = slab + rw * DROW;
            float* d1 = d0 + 8 * DROW;
            #pragma unroll
            for (int jt = 0; jt < 10; ++jt) {
                const int ja = jt * 8 + 2 * g;
                float4 ca = d0c[ja], cb = d0c[ja + 1];
                float v00 = dice4(acc[jt][0], ca);
                float v01 = dice4(acc[jt][1], cb);
                float v10 = dice4(acc[jt][2], ca);
                float v11 = dice4(acc[jt][3], cb);
                *(float2*)(d0 + ja) = make_float2(
                    __uint_as_float(cvt_tf32(v00)), __uint_as_float(cvt_tf32(v01)));
                *(float2*)(d1 + ja) = make_float2(
                    __uint_as_float(cvt_tf32(v10)), __uint_as_float(cvt_tf32(v11)));
            }
            __syncwarp();

            // ---- layer 1: h[16x40] = D[16x80] @ W1[80x40], A-frags from slab ----
            uint af[10][4];
            #pragma unroll
            for (int kt = 0; kt < 10; ++kt) {
                af[kt][0] = __float_as_uint(d0[8 * kt + g]);
                af[kt][1] = __float_as_uint(d1[8 * kt + g]);
                af[kt][2] = __float_as_uint(d0[8 * kt + g + 4]);
                af[kt][3] = __float_as_uint(d1[8 * kt + g + 4]);
            }
            float hc[5][4];
            #pragma unroll
            for (int jt = 0; jt < 5; ++jt)
                hc[jt][0] = hc[jt][1] = hc[jt][2] = hc[jt][3] = 0.0f;

            const float* wbase = W1c + rw * WROW + 2 * g;
            #pragma unroll
            for (int kt = 0; kt < 10; ++kt) {
                const float* wk = wbase + 8 * kt;
                #pragma unroll
                for (int jt = 0; jt < 5; ++jt) {
                    // (b0,b1) = W1[kt*8+g][jt*8+rw], W1[kt*8+g+4][jt*8+rw]
                    float2 bw = *(const float2*)(wk + jt * 8 * WROW);
                    mma16n8k8(hc[jt][0], hc[jt][1], hc[jt][2], hc[jt][3],
                              af[kt][0], af[kt][1], af[kt][2], af[kt][3],
                              __float_as_uint(bw.x), __float_as_uint(bw.y));
                }
            }
            // epilogue: dice1(+ak folded), accumulate row sums
            float s0 = 0.0f, s1 = 0.0f;
            #pragma unroll
            for (int jt = 0; jt < 5; ++jt) {
                const int ja = jt * 8 + 2 * g;
                float4 ca = d1c[ja], cb = d1c[ja + 1];
                float  ba = b1d[ja], bb = b1d[ja + 1];
                float c0 = hc[jt][0], c1 = hc[jt][1];
                float c2 = hc[jt][2], c3 = hc[jt][3];
                s0 += (c0 + ba) * fmaf(ca.y, tanhx(fmaf(c0, ca.z, ca.w)), ca.x)
                    + (c1 + bb) * fmaf(cb.y, tanhx(fmaf(c1, cb.z, cb.w)), cb.x);
                s1 += (c2 + ba) * fmaf(ca.y, tanhx(fmaf(c2, ca.z, ca.w)), ca.x)
                    + (c3 + bb) * fmaf(cb.y, tanhx(fmaf(c3, cb.z, cb.w)), cb.x);
            }
            // reduce over the 4 lanes (g) sharing each row; rows warp-exclusive
            s0 += __shfl_xor_sync(0xFFFFFFFF, s0, 1);
            s0 += __shfl_xor_sync(0xFFFFFFFF, s0, 2);
            s1 += __shfl_xor_sync(0xFFFFFFFF, s1, 1);
            s1 += __shfl_xor_sync(0xFFFFFFFF, s1, 2);
            if (g == 0) {
                sc[r0] = score0 + s0;   // r0 = pt*16+rw
                sc[r1] = score0 + s1;
            }
            __syncwarp();  // WAR: slab reused by next tile
        }
    }
    __syncthreads();

    // ===================== Final: out[b][e] = sum_t sc[t] * keys[b][t][e] ======
    // (UNMASKED scores, reproducing the reference bug faithfully)
    if (tid < 96) {
        int e = tid % 12;
        int c = tid / 12;     // 8 chunks of 25 positions
        float acc = 0.0f;
        int t0 = c * 25;
        #pragma unroll 5
        for (int t2 = t0; t2 < t0 + 25; ++t2)
            acc = fmaf(sc[t2], ksh[t2 * 12 + e], acc);
        psum[tid] = acc;
    }
    __syncthreads();
    if (tid < 12) {
        float acc = 0.0f;
        #pragma unroll
        for (int c = 0; c < 8; ++c) acc += psum[c * 12 + tid];
        out[b * 12 + tid] = acc;
    }
}

extern "C" void kernel_launch(void* const* d_in, const int* in_sizes, int n_in,
                              void* d_out, int out_size) {
    const float* query  = (const float*)d_in[0];
    const float* keys   = (const float*)d_in[1];
    // d_in[2] = mask (bool) -- intentionally unused: reference overwrites the
    // masked scores and matmuls the UNMASKED scores (bug reproduced faithfully)
    const float* W0     = (const float*)d_in[3];
    const float* b0     = (const float*)d_in[4];
    const float* W1     = (const float*)d_in[5];
    const float* b1     = (const float*)d_in[6];
    const float* alpha0 = (const float*)d_in[7];
    const float* alpha1 = (const float*)d_in[8];
    const float* mm0    = (const float*)d_in[9];
    const float* mv0    = (const float*)d_in[10];
    const float* mm1    = (const float*)d_in[11];
    const float* mv1    = (const float*)d_in[12];
    const float* ak     = (const float*)d_in[13];
    const float* ab     = (const float*)d_in[14];
    float* out = (float*)d_out;

    // idempotent attribute set, not a stream op -> graph-capture safe
    cudaFuncSetAttribute(din_kernel, cudaFuncAttributeMaxDynamicSharedMemorySize,
                         SMEM_BYTES);

    int B = out_size / 12;  // [B, 1, 12]
    din_kernel<<<B, NT, SMEM_BYTES>>>(query, keys, W0, b0, W1, b1, alpha0, alpha1,
                                      mm0, mv0, mm1, mv1, ak, ab, out);
}

// round 10
// speedup vs baseline: 2.5580x; 1.1845x over previous
#include <cuda_runtime.h>

typedef unsigned int uint;

__device__ __forceinline__ float tanhx(float x) {
    float y; asm("tanh.approx.f32 %0, %1;" : "=f"(y) : "f"(x)); return y;
}
__device__ __forceinline__ uint cvt_tf32(float x) {
    uint r; asm("cvt.rna.tf32.f32 %0, %1;" : "=r"(r) : "f"(x)); return r;
}
// Dice via tanh: dice(x) = x * fma(C2, tanh(fma(x, S2, MS2)), A2)
__device__ __forceinline__ float dice4(float x, float4 c) {
    return x * fmaf(c.y, tanhx(fmaf(x, c.z, c.w)), c.x);
}
// m16n8k8 tf32 warp MMA (A row-major, B col-major, fp32 accum)
__device__ __forceinline__ void mma16n8k8(float& d0, float& d1, float& d2, float& d3,
                                          uint a0, uint a1, uint a2, uint a3,
                                          uint b0, uint b1) {
    asm("mma.sync.aligned.m16n8k8.row.col.f32.tf32.tf32.f32 "
        "{%0,%1,%2,%3}, {%4,%5,%6,%7}, {%8,%9}, {%0,%1,%2,%3};"
        : "+f"(d0), "+f"(d1), "+f"(d2), "+f"(d3)
        : "r"(a0), "r"(a1), "r"(a2), "r"(a3), "r"(b0), "r"(b1));
}
// slot interleave within each 8-index block: (8m+g, 8m+g+4) -> (8m+2g, 8m+2g+1)
__device__ __forceinline__ int slot_of(int c) {
    return (c & ~7) + 2 * (c & 3) + ((c >> 2) & 1);
}

static constexpr int NT     = 416;                // 13 warps = 13 tiles, 1 each
static constexpr int WROW   = 84;                 // W1c row stride
static constexpr int MROW   = 24;                 // Mtc row stride
// Shared layout (floats):
static constexpr int O_KSH  = 0;                  // ksh [208][12]       2496
static constexpr int O_W1C  = O_KSH + 2496;       // W1c [40][84]        3360
static constexpr int O_MTC  = O_W1C + 40*WROW;    // Mtc [80][24]        1920
static constexpr int O_D0C  = O_MTC + 80*MROW;    // d0c float4[80]      320
static constexpr int O_D1C  = O_D0C + 320;        // d1c float4[40]      160
static constexpr int O_B1D  = O_D1C + 160;        // b1d [40]            40
static constexpr int O_SC   = O_B1D + 40;         // sc [208]            208
static constexpr int O_PSUM = O_SC + 208;         // psum [96]           96
static constexpr int O_QS   = O_PSUM + 96;        // qs [12]             12
static constexpr int O_SC0  = O_QS + 12;          // score0 (+pad)       4
static constexpr int SMEM_FLOATS = O_SC0 + 4;     // 8616
static constexpr int SMEM_BYTES  = SMEM_FLOATS * 4;   // 34464 B

__global__ void __launch_bounds__(NT, 2) din_kernel(
    const float* __restrict__ query, const float* __restrict__ keys,
    const float* __restrict__ W0, const float* __restrict__ b0,
    const float* __restrict__ W1, const float* __restrict__ b1,
    const float* __restrict__ alpha0, const float* __restrict__ alpha1,
    const float* __restrict__ mm0, const float* __restrict__ mv0,
    const float* __restrict__ mm1, const float* __restrict__ mv1,
    const float* __restrict__ ak, const float* __restrict__ ab,
    float* __restrict__ out)
{
    extern __shared__ __align__(16) float smf[];
    float*  ksh  = smf + O_KSH;      // keys natural [208][12], rows 200-207 zero
    float*  W1c  = smf + O_W1C;      // W1c[j*84 + slot(k)] = tf32(W1[k][j])
    float*  Mtc  = smf + O_MTC;      // Mtc[slot(o)*24 + slot(k)] = tf32(M[k][o])
    float4* d0c  = (float4*)(smf + O_D0C);   // natural channel order
    float4* d1c  = (float4*)(smf + O_D1C);
    float*  b1d  = smf + O_B1D;
    float*  sc   = smf + O_SC;
    float*  psum = smf + O_PSUM;
    float*  qs   = smf + O_QS;

    const int tid  = threadIdx.x;
    const int b    = blockIdx.x;
    const int wid  = tid >> 5;
    const int lane = tid & 31;
    const int g    = lane & 3;    // k/n group
    const int rw   = lane >> 2;   // row within fragment
    const float EPS = 1e-9f;

    if (tid < 12) qs[tid] = query[b * 12 + tid];
    if (tid == 0) smf[O_SC0] = ab[0];
    __syncthreads();  // qs needed by Mtc fill

    // ===================== Phase A: cooperative precompute =====================
    // keys: natural layout, float4 copy; zero pad rows 200..207
    {
        const float4* gk = (const float4*)(keys + (size_t)b * 2400);
        float4* sk = (float4*)ksh;
        for (int i = tid; i < 600; i += NT) sk[i] = gk[i];
        if (tid < 96) ksh[2400 + tid] = 0.0f;
    }
    // W1 -> transposed, k-slot interleaved, tf32 (400 threads x 8)
    if (tid < 400) {
        int j = tid % 40, k0 = tid / 40;   // k0 in 0..9
        #pragma unroll
        for (int it = 0; it < 8; ++it) {
            int k = k0 + 10 * it;
            W1c[j * WROW + slot_of(k)] = __uint_as_float(cvt_tf32(W1[k * 40 + j]));
        }
    }
    // Mtc rows: logical channel o stored at PHYSICAL row slot_of(o), so the
    // layer-0 accumulator comes out directly in layer-1 A-fragment order.
    // M[k][o] = W0[12+k][o] - W0[24+k][o] + q_k * W0[36+k][o]
    if (tid < 320) {
        int o = tid % 80, kg = tid / 80;   // kg in 0..3
        int prow = slot_of(o) * MROW;
        #pragma unroll
        for (int kk = 0; kk < 3; ++kk) {
            int k = kg * 3 + kk;
            float m = W0[(12 + k) * 80 + o] - W0[(24 + k) * 80 + o]
                    + qs[k] * W0[(36 + k) * 80 + o];
            Mtc[prow + slot_of(k)] = __uint_as_float(cvt_tf32(m));
        }
    }
    // Mtc row k=12 (slot 9) = base[o]; zero k=13..15 (slots 11,13,15); d0c.
    if (tid < 80) {
        int o = tid;
        float s = b0[o];
        #pragma unroll
        for (int i = 0; i < 12; ++i)
            s += qs[i] * (W0[i * 80 + o] + W0[(24 + i) * 80 + o]);
        int prow = slot_of(o) * MROW;
        Mtc[prow + 9]  = __uint_as_float(cvt_tf32(s));
        Mtc[prow + 11] = 0.0f;
        Mtc[prow + 13] = 0.0f;
        Mtc[prow + 15] = 0.0f;
        float a  = alpha0[o];
        float c2 = 0.5f * (1.0f - a);
        float s2 = 0.5f * rsqrtf(mv0[o] + EPS);
        d0c[o] = make_float4(a + c2, c2, s2, -mm0[o] * s2);
    }
    // dice1 constants with ak folded; MS2' absorbs b1 shift (z uses raw acc c)
    if (tid < 40) {
        int o = tid;
        float a  = alpha1[o];
        float kk = ak[o];
        float c2 = 0.5f * (1.0f - a);
        float s2 = 0.5f * rsqrtf(mv1[o] + EPS);
        d1c[o] = make_float4((a + c2) * kk, c2 * kk, s2, (b1[o] - mm1[o]) * s2);
        b1d[o] = b1[o];
    }
    __syncthreads();

    // ===== Fused tile (1 per warp): layer0 HMMA -> in-register dice0 -> layer1 =
    {
        const float score0 = smf[O_SC0];
        const int pt = wid;                       // 13 warps, 13 tiles
        const int r0 = pt * 16 + rw, r1 = r0 + 8;

        // ---- layer 0: X[16x80] = K[16x16] @ M[16x80] (bias ones-column) ----
        const float* k0p = ksh + r0 * 12;
        const float* k1p = ksh + r1 * 12;
        uint ka0 = cvt_tf32(k0p[g]),     ka1 = cvt_tf32(k1p[g]);
        uint ka2 = cvt_tf32(k0p[g + 4]), ka3 = cvt_tf32(k1p[g + 4]);
        uint kb0 = cvt_tf32(k0p[8 + g]), kb1 = cvt_tf32(k1p[8 + g]);
        uint one = (g == 0) ? 0x3F800000u : 0u;   // logical k=12 = bias row

        float acc[10][4];
        #pragma unroll
        for (int jt = 0; jt < 10; ++jt)
            acc[jt][0] = acc[jt][1] = acc[jt][2] = acc[jt][3] = 0.0f;

        #pragma unroll
        for (int jt = 0; jt < 10; ++jt) {
            const float* mrow = Mtc + (jt * 8 + rw) * MROW + 2 * g;
            float2 w0 = *(const float2*)(mrow);       // logical k: g, g+4
            float2 w1 = *(const float2*)(mrow + 8);   // logical k: 8+g, 12+g
            mma16n8k8(acc[jt][0], acc[jt][1], acc[jt][2], acc[jt][3],
                      ka0, ka1, ka2, ka3,
                      __float_as_uint(w0.x), __float_as_uint(w0.y));
            mma16n8k8(acc[jt][0], acc[jt][1], acc[jt][2], acc[jt][3],
                      kb0, kb1, one, one,
                      __float_as_uint(w1.x), __float_as_uint(w1.y));
        }

        // ---- dice0 in-register; acc (slot-permuted channels) IS the A-frag ----
        // acc[jt] = x(rw, 8jt+g), x(rw, 8jt+g+4), x(rw+8, 8jt+g), x(rw+8, 8jt+g+4)
        // layer-1 A-frag af[jt] = D[rw][8jt+g], D[rw+8][8jt+g], D[rw][8jt+g+4], D[rw+8][8jt+g+4]
        uint af[10][4];
        #pragma unroll
        for (int jt = 0; jt < 10; ++jt) {
            float4 ca = d0c[8 * jt + g];
            float4 cb = d0c[8 * jt + g + 4];
            af[jt][0] = cvt_tf32(dice4(acc[jt][0], ca));
            af[jt][1] = cvt_tf32(dice4(acc[jt][2], ca));
            af[jt][2] = cvt_tf32(dice4(acc[jt][1], cb));
            af[jt][3] = cvt_tf32(dice4(acc[jt][3], cb));
        }

        // ---- layer 1: h[16x40] = D[16x80] @ W1[80x40] ----
        float hc[5][4];
        #pragma unroll
        for (int jt = 0; jt < 5; ++jt)
            hc[jt][0] = hc[jt][1] = hc[jt][2] = hc[jt][3] = 0.0f;

        const float* wbase = W1c + rw * WROW + 2 * g;
        #pragma unroll
        for (int kt = 0; kt < 10; ++kt) {
            const float* wk = wbase + 8 * kt;
            #pragma unroll
            for (int jt = 0; jt < 5; ++jt) {
                // (b0,b1) = W1[kt*8+g][jt*8+rw], W1[kt*8+g+4][jt*8+rw]
                float2 bw = *(const float2*)(wk + jt * 8 * WROW);
                mma16n8k8(hc[jt][0], hc[jt][1], hc[jt][2], hc[jt][3],
                          af[kt][0], af[kt][1], af[kt][2], af[kt][3],
                          __float_as_uint(bw.x), __float_as_uint(bw.y));
            }
        }

        // ---- epilogue: dice1(+ak folded), row sums, 4-lane reduce ----
        float s0 = 0.0f, s1 = 0.0f;
        #pragma unroll
        for (int jt = 0; jt < 5; ++jt) {
            const int ja = jt * 8 + 2 * g;
            float4 ca = d1c[ja], cb = d1c[ja + 1];
            float  ba = b1d[ja], bb = b1d[ja + 1];
            float c0 = hc[jt][0], c1 = hc[jt][1];
            float c2 = hc[jt][2], c3 = hc[jt][3];
            s0 += (c0 + ba) * fmaf(ca.y, tanhx(fmaf(c0, ca.z, ca.w)), ca.x)
                + (c1 + bb) * fmaf(cb.y, tanhx(fmaf(c1, cb.z, cb.w)), cb.x);
            s1 += (c2 + ba) * fmaf(ca.y, tanhx(fmaf(c2, ca.z, ca.w)), ca.x)
                + (c3 + bb) * fmaf(cb.y, tanhx(fmaf(c3, cb.z, cb.w)), cb.x);
        }
        s0 += __shfl_xor_sync(0xFFFFFFFF, s0, 1);
        s0 += __shfl_xor_sync(0xFFFFFFFF, s0, 2);
        s1 += __shfl_xor_sync(0xFFFFFFFF, s1, 1);
        s1 += __shfl_xor_sync(0xFFFFFFFF, s1, 2);
        if (g == 0) {
            sc[r0] = score0 + s0;
            sc[r1] = score0 + s1;
        }
    }
    __syncthreads();

    // ===================== Final: out[b][e] = sum_t sc[t] * keys[b][t][e] ======
    // (UNMASKED scores, reproducing the reference bug faithfully)
    if (tid < 96) {
        int e = tid % 12;
        int c = tid / 12;     // 8 chunks of 25 positions
        float acc = 0.0f;
        int t0 = c * 25;
        #pragma unroll 5
        for (int t2 = t0; t2 < t0 + 25; ++t2)
            acc = fmaf(sc[t2], ksh[t2 * 12 + e], acc);
        psum[tid] = acc;
    }
    __syncthreads();
    if (tid < 12) {
        float acc = 0.0f;
        #pragma unroll
        for (int c = 0; c < 8; ++c) acc += psum[c * 12 + tid];
        out[b * 12 + tid] = acc;
    }
}

extern "C" void kernel_launch(void* const* d_in, const int* in_sizes, int n_in,
                              void* d_out, int out_size) {
    const float* query  = (const float*)d_in[0];
    const float* keys   = (const float*)d_in[1];
    // d_in[2] = mask (bool) -- intentionally unused: reference overwrites the
    // masked scores and matmuls the UNMASKED scores (bug reproduced faithfully)
    const float* W0     = (const float*)d_in[3];
    const float* b0     = (const float*)d_in[4];
    const float* W1     = (const float*)d_in[5];
    const float* b1     = (const float*)d_in[6];
    const float* alpha0 = (const float*)d_in[7];
    const float* alpha1 = (const float*)d_in[8];
    const float* mm0    = (const float*)d_in[9];
    const float* mv0    = (const float*)d_in[10];
    const float* mm1    = (const float*)d_in[11];
    const float* mv1    = (const float*)d_in[12];
    const float* ak     = (const float*)d_in[13];
    const float* ab     = (const float*)d_in[14];
    float* out = (float*)d_out;

    // idempotent attribute set, not a stream op -> graph-capture safe
    cudaFuncSetAttribute(din_kernel, cudaFuncAttributeMaxDynamicSharedMemorySize,
                         SMEM_BYTES);

    int B = out_size / 12;  // [B, 1, 12]
    din_kernel<<<B, NT, SMEM_BYTES>>>(query, keys, W0, b0, W1, b1, alpha0, alpha1,
                                      mm0, mv0, mm1, mv1, ak, ab, out);
}

// round 11
// speedup vs baseline: 2.7859x; 1.0891x over previous
#include <cuda_runtime.h>

typedef unsigned int uint;

__device__ __forceinline__ float tanhx(float x) {
    float y; asm("tanh.approx.f32 %0, %1;" : "=f"(y) : "f"(x)); return y;
}
__device__ __forceinline__ uint cvt_tf32(float x) {
    uint r; asm("cvt.rna.tf32.f32 %0, %1;" : "=r"(r) : "f"(x)); return r;
}
// Dice via tanh: dice(x) = x * fma(C2, tanh(fma(x, S2, MS2)), A2)
__device__ __forceinline__ float dice4(float x, float4 c) {
    return x * fmaf(c.y, tanhx(fmaf(x, c.z, c.w)), c.x);
}
// m16n8k8 tf32 warp MMA (A row-major, B col-major, fp32 accum)
__device__ __forceinline__ void mma16n8k8(float& d0, float& d1, float& d2, float& d3,
                                          uint a0, uint a1, uint a2, uint a3,
                                          uint b0, uint b1) {
    asm("mma.sync.aligned.m16n8k8.row.col.f32.tf32.tf32.f32 "
        "{%0,%1,%2,%3}, {%4,%5,%6,%7}, {%8,%9}, {%0,%1,%2,%3};"
        : "+f"(d0), "+f"(d1), "+f"(d2), "+f"(d3)
        : "r"(a0), "r"(a1), "r"(a2), "r"(a3), "r"(b0), "r"(b1));
}
// slot interleave within each 8-index block: (8m+g, 8m+g+4) -> (8m+2g, 8m+2g+1)
__device__ __forceinline__ int slot_of(int c) {
    return (c & ~7) + 2 * (c & 3) + ((c >> 2) & 1);
}
// inverse of slot_of within each 8-block
__device__ __forceinline__ int unslot(int s) {
    return (s & ~7) + ((s & 7) >> 1) + 4 * (s & 1);
}

static constexpr int NT   = 416;     // 13 warps = 13 tiles
static constexpr int WROW = 88;      // W1c stride: rw*88 mod 32 = {0,24,16,8} conflict-free
static constexpr int MROW = 24;      // Mtc stride

// ---- batch-independent precomputed images (written by setup_kernel) ----
__device__ float  g_W1c[40 * WROW];  // exact W1c shared image (tf32 bits)
__device__ float  g_Wk [80 * MROW];  // Mtc-layout image of W0[12+k][o]-W0[24+k][o]
__device__ float  g_Wq [80 * MROW];  // Mtc-layout image of W0[36+k][o]
__device__ float  g_Wbt[80 * 12];    // Wbt[o*12+i] = W0[i][o] + W0[24+i][o]
__device__ float4 g_cst[130];        // [0..79]=d0c, [80..119]=d1c, [120..129]=b1 (10xf4)

__global__ void setup_kernel(
    const float* __restrict__ W0, const float* __restrict__ W1,
    const float* __restrict__ b1,
    const float* __restrict__ alpha0, const float* __restrict__ alpha1,
    const float* __restrict__ mm0, const float* __restrict__ mv0,
    const float* __restrict__ mm1, const float* __restrict__ mv1,
    const float* __restrict__ ak)
{
    const int tid = threadIdx.x;
    const float EPS = 1e-9f;
    // W1c image: row j (0..39) x 88 cols; col c<80 holds tf32(W1[unslot(c)][j])
    for (int idx = tid; idx < 40 * WROW; idx += 256) {
        int j = idx / WROW, c = idx % WROW;
        float v = 0.0f;
        if (c < 80) {
            int k = unslot(c);
            v = __uint_as_float(cvt_tf32(W1[k * 40 + j]));
        }
        g_W1c[idx] = v;
    }
    // Wk/Wq images in final Mtc layout: phys row po=slot(o), col s=slot(k); k>=12 -> 0
    for (int idx = tid; idx < 80 * MROW; idx += 256) {
        int po = idx / MROW, s = idx % MROW;
        int o = unslot(po);
        float wk = 0.0f, wq = 0.0f;
        if (s < 16) {
            int k = unslot(s);
            if (k < 12) {
                wk = W0[(12 + k) * 80 + o] - W0[(24 + k) * 80 + o];
                wq = W0[(36 + k) * 80 + o];
            }
        }
        g_Wk[idx] = wk;
        g_Wq[idx] = wq;
    }
    // Wbt transposed: Wbt[o*12+i] = W0[i][o] + W0[24+i][o]
    for (int idx = tid; idx < 960; idx += 256) {
        int o = idx / 12, i = idx % 12;
        g_Wbt[idx] = W0[i * 80 + o] + W0[(24 + i) * 80 + o];
    }
    // dice constants
    if (tid < 80) {
        float a  = alpha0[tid];
        float c2 = 0.5f * (1.0f - a);
        float s2 = 0.5f * rsqrtf(mv0[tid] + EPS);
        g_cst[tid] = make_float4(a + c2, c2, s2, -mm0[tid] * s2);
    }
    if (tid >= 128 && tid < 168) {
        int o = tid - 128;
        float a  = alpha1[o];
        float kk = ak[o];
        float c2 = 0.5f * (1.0f - a);
        float s2 = 0.5f * rsqrtf(mv1[o] + EPS);
        g_cst[80 + o] = make_float4((a + c2) * kk, c2 * kk, s2, (b1[o] - mm1[o]) * s2);
    }
    if (tid >= 192 && tid < 202) {
        int p = tid - 192;
        g_cst[120 + p] = make_float4(b1[4*p], b1[4*p+1], b1[4*p+2], b1[4*p+3]);
    }
}

// Shared layout (floats):
static constexpr int O_KSH   = 0;                     // ksh [208][12]    2496
static constexpr int O_W1C   = 2496;                  // W1c [40][88]     3520
static constexpr int O_MTC   = O_W1C + 40*WROW;       // Mtc [80][24]     1920
static constexpr int O_CST   = O_MTC + 80*MROW;       // d0c|d1c|b1d      520
static constexpr int O_BASE  = O_CST + 520;           // base [80]        80
static constexpr int O_SC    = O_BASE + 80;           // sc [208]         208
static constexpr int O_PSUM  = O_SC + 208;            // psum [192]       192
static constexpr int O_QS    = O_PSUM + 192;          // qs [12]          12
static constexpr int O_QSLOT = O_QS + 12;             // qslot [24]       24
static constexpr int O_SC0   = O_QSLOT + 24;          // score0 (+pad)    4
static constexpr int SMEM_FLOATS = O_SC0 + 4;         // 8980
static constexpr int SMEM_BYTES  = SMEM_FLOATS * 4;   // 35920 B -> 2 CTAs/SM

__global__ void __launch_bounds__(NT, 2) din_kernel(
    const float* __restrict__ query, const float* __restrict__ keys,
    const float* __restrict__ b0, const float* __restrict__ ab,
    float* __restrict__ out)
{
    extern __shared__ __align__(16) float smf[];
    float*  ksh   = smf + O_KSH;     // keys natural [208][12], rows 200-207 zero
    float*  W1c   = smf + O_W1C;
    float*  Mtc   = smf + O_MTC;
    float4* d0c   = (float4*)(smf + O_CST);
    float4* d1c   = (float4*)(smf + O_CST + 320);
    float*  b1d   = smf + O_CST + 480;
    float*  basef = smf + O_BASE;
    float*  sc    = smf + O_SC;
    float*  psum  = smf + O_PSUM;
    float*  qs    = smf + O_QS;
    float*  qslot = smf + O_QSLOT;

    const int tid  = threadIdx.x;
    const int b    = blockIdx.x;
    const int wid  = tid >> 5;
    const int lane = tid & 31;
    const int g    = lane & 3;    // k/n group
    const int rw   = lane >> 2;   // row within fragment

    if (tid < 12) qs[tid] = query[b * 12 + tid];
    if (tid == 0) smf[O_SC0] = ab[0];
    __syncthreads();  // qs ready

    // ============ Phase A stage 1: copies + base + qslot ============
    {
        const float4* gk = (const float4*)(keys + (size_t)b * 2400);
        float4* sk = (float4*)ksh;
        for (int i = tid; i < 600; i += NT) sk[i] = gk[i];
        if (tid < 96) ksh[2400 + tid] = 0.0f;
    }
    {
        const float4* src = (const float4*)g_W1c;
        float4* dst = (float4*)W1c;
        for (int i = tid; i < (40 * WROW) / 4; i += NT) dst[i] = src[i];
    }
    if (tid < 130) ((float4*)(smf + O_CST))[tid] = g_cst[tid];
    if (tid < 24) {
        float v = 0.0f;
        if (tid < 16) { int k = unslot(tid); if (k < 12) v = qs[k]; }
        qslot[tid] = v;
    }
    if (tid < 80) {
        float s = b0[tid];
        const float4* wb = (const float4*)(g_Wbt + tid * 12);
        float4 w0v = wb[0], w1v = wb[1], w2v = wb[2];
        s += qs[0]*w0v.x + qs[1]*w0v.y + qs[2]*w0v.z  + qs[3]*w0v.w
           + qs[4]*w1v.x + qs[5]*w1v.y + qs[6]*w1v.z  + qs[7]*w1v.w
           + qs[8]*w2v.x + qs[9]*w2v.y + qs[10]*w2v.z + qs[11]*w2v.w;
        basef[tid] = s;
    }
    __syncthreads();

    // ============ Phase A stage 2: Mtc = cvt_tf32(Wk + q*Wq) ============
    for (int i = tid; i < 480; i += NT) {
        float4 wk = ((const float4*)g_Wk)[i];
        float4 wq = ((const float4*)g_Wq)[i];
        float4 q4 = ((const float4*)qslot)[i % 6];
        float4 v;
        v.x = __uint_as_float(cvt_tf32(fmaf(q4.x, wq.x, wk.x)));
        v.y = __uint_as_float(cvt_tf32(fmaf(q4.y, wq.y, wk.y)));
        v.z = __uint_as_float(cvt_tf32(fmaf(q4.z, wq.z, wk.z)));
        v.w = __uint_as_float(cvt_tf32(fmaf(q4.w, wq.w, wk.w)));
        ((float4*)Mtc)[i] = v;
    }
    __syncthreads();

    // ===== Fused tile (1 per warp): layer0 HMMA -> in-register dice0 -> layer1 =
    {
        const float score0 = smf[O_SC0];
        const int pt = wid;                       // 13 warps, 13 tiles
        const int r0 = pt * 16 + rw, r1 = r0 + 8;

        // ---- layer 0: X[16x80] = K[16x16] @ M[16x80]; bias via acc init ----
        const float* k0p = ksh + r0 * 12;
        const float* k1p = ksh + r1 * 12;
        uint ka0 = cvt_tf32(k0p[g]),     ka1 = cvt_tf32(k1p[g]);
        uint ka2 = cvt_tf32(k0p[g + 4]), ka3 = cvt_tf32(k1p[g + 4]);
        uint kb0 = cvt_tf32(k0p[8 + g]), kb1 = cvt_tf32(k1p[8 + g]);

        float acc[10][4];
        #pragma unroll
        for (int jt = 0; jt < 10; ++jt) {
            float bA = basef[8 * jt + g];       // broadcast LDS
            float bB = basef[8 * jt + g + 4];
            acc[jt][0] = bA; acc[jt][2] = bA;   // cols o=8jt+g (rows rw, rw+8)
            acc[jt][1] = bB; acc[jt][3] = bB;   // cols o=8jt+g+4
        }

        #pragma unroll
        for (int jt = 0; jt < 10; ++jt) {
            const float* mrow = Mtc + (jt * 8 + rw) * MROW + 2 * g;
            float2 w0 = *(const float2*)(mrow);       // logical k: g, g+4
            float2 w1 = *(const float2*)(mrow + 8);   // logical k: 8+g, (12+g -> 0)
            mma16n8k8(acc[jt][0], acc[jt][1], acc[jt][2], acc[jt][3],
                      ka0, ka1, ka2, ka3,
                      __float_as_uint(w0.x), __float_as_uint(w0.y));
            mma16n8k8(acc[jt][0], acc[jt][1], acc[jt][2], acc[jt][3],
                      kb0, kb1, 0u, 0u,
                      __float_as_uint(w1.x), __float_as_uint(w1.y));
        }

        // ---- dice0 in-register; acc (slot-permuted channels) IS the A-frag ----
        uint af[10][4];
        #pragma unroll
        for (int jt = 0; jt < 10; ++jt) {
            float4 ca = d0c[8 * jt + g];
            float4 cb = d0c[8 * jt + g + 4];
            af[jt][0] = cvt_tf32(dice4(acc[jt][0], ca));
            af[jt][1] = cvt_tf32(dice4(acc[jt][2], ca));
            af[jt][2] = cvt_tf32(dice4(acc[jt][1], cb));
            af[jt][3] = cvt_tf32(dice4(acc[jt][3], cb));
        }

        // ---- layer 1: h[16x40] = D[16x80] @ W1[80x40] ----
        float hc[5][4];
        #pragma unroll
        for (int jt = 0; jt < 5; ++jt)
            hc[jt][0] = hc[jt][1] = hc[jt][2] = hc[jt][3] = 0.0f;

        const float* wbase = W1c + rw * WROW + 2 * g;
        #pragma unroll
        for (int kt = 0; kt < 10; ++kt) {
            const float* wk = wbase + 8 * kt;
            #pragma unroll
            for (int jt = 0; jt < 5; ++jt) {
                // (b0,b1) = W1[kt*8+g][jt*8+rw], W1[kt*8+g+4][jt*8+rw]
                float2 bw = *(const float2*)(wk + jt * 8 * WROW);
                mma16n8k8(hc[jt][0], hc[jt][1], hc[jt][2], hc[jt][3],
                          af[kt][0], af[kt][1], af[kt][2], af[kt][3],
                          __float_as_uint(bw.x), __float_as_uint(bw.y));
            }
        }

        // ---- epilogue: dice1(+ak folded), row sums, 4-lane reduce ----
        float s0 = 0.0f, s1 = 0.0f;
        #pragma unroll
        for (int jt = 0; jt < 5; ++jt) {
            const int ja = jt * 8 + 2 * g;
            float4 ca = d1c[ja], cb = d1c[ja + 1];
            float2 bb2 = *(const float2*)(b1d + ja);
            float c0 = hc[jt][0], c1 = hc[jt][1];
            float c2 = hc[jt][2], c3 = hc[jt][3];
            s0 += (c0 + bb2.x) * fmaf(ca.y, tanhx(fmaf(c0, ca.z, ca.w)), ca.x)
                + (c1 + bb2.y) * fmaf(cb.y, tanhx(fmaf(c1, cb.z, cb.w)), cb.x);
            s1 += (c2 + bb2.x) * fmaf(ca.y, tanhx(fmaf(c2, ca.z, ca.w)), ca.x)
                + (c3 + bb2.y) * fmaf(cb.y, tanhx(fmaf(c3, cb.z, cb.w)), cb.x);
        }
        s0 += __shfl_xor_sync(0xFFFFFFFF, s0, 1);
        s0 += __shfl_xor_sync(0xFFFFFFFF, s0, 2);
        s1 += __shfl_xor_sync(0xFFFFFFFF, s1, 1);
        s1 += __shfl_xor_sync(0xFFFFFFFF, s1, 2);
        if (g == 0) {
            sc[r0] = score0 + s0;
            sc[r1] = score0 + s1;
        }
    }
    __syncthreads();

    // ===================== Final: out[b][e] = sum_t sc[t] * keys[b][t][e] ======
    // (UNMASKED scores, reproducing the reference bug faithfully.)
    // Rows 200..207: ksh is zero there, so their products contribute 0.
    if (tid < 192) {
        int e = tid % 12;
        int c = tid / 12;     // 16 chunks of 13 positions (16*13 = 208)
        float acc = 0.0f;
        int t0 = c * 13;
        #pragma unroll
        for (int t2 = t0; t2 < t0 + 13; ++t2)
            acc = fmaf(sc[t2], ksh[t2 * 12 + e], acc);
        psum[tid] = acc;
    }
    __syncthreads();
    if (tid < 12) {
        float acc = 0.0f;
        #pragma unroll
        for (int c = 0; c < 16; ++c) acc += psum[c * 12 + tid];
        out[b * 12 + tid] = acc;
    }
}

extern "C" void kernel_launch(void* const* d_in, const int* in_sizes, int n_in,
                              void* d_out, int out_size) {
    const float* query  = (const float*)d_in[0];
    const float* keys   = (const float*)d_in[1];
    // d_in[2] = mask (bool) -- intentionally unused: reference overwrites the
    // masked scores and matmuls the UNMASKED scores (bug reproduced faithfully)
    const float* W0     = (const float*)d_in[3];
    const float* b0     = (const float*)d_in[4];
    const float* W1     = (const float*)d_in[5];
    const float* b1     = (const float*)d_in[6];
    const float* alpha0 = (const float*)d_in[7];
    const float* alpha1 = (const float*)d_in[8];
    const float* mm0    = (const float*)d_in[9];
    const float* mv0    = (const float*)d_in[10];
    const float* mm1    = (const float*)d_in[11];
    const float* mv1    = (const float*)d_in[12];
    const float* ak     = (const float*)d_in[13];
    const float* ab     = (const float*)d_in[14];
    float* out = (float*)d_out;

    // idempotent attribute set, not a stream op -> graph-capture safe
    cudaFuncSetAttribute(din_kernel, cudaFuncAttributeMaxDynamicSharedMemorySize,
                         SMEM_BYTES);

    // batch-independent precompute (deterministic; same stream -> ordered)
    setup_kernel<<<1, 256>>>(W0, W1, b1, alpha0, alpha1, mm0, mv0, mm1, mv1, ak);

    int B = out_size / 12;  // [B, 1, 12]
    din_kernel<<<B, NT, SMEM_BYTES>>>(query, keys, b0, ab, out);
}

// round 12
// speedup vs baseline: 3.0561x; 1.0970x over previous
#include <cuda_runtime.h>

typedef unsigned int uint;

__device__ __forceinline__ float tanhx(float x) {
    float y; asm("tanh.approx.f32 %0, %1;" : "=f"(y) : "f"(x)); return y;
}
__device__ __forceinline__ uint cvt_tf32(float x) {
    uint r; asm("cvt.rna.tf32.f32 %0, %1;" : "=r"(r) : "f"(x)); return r;
}
// Dice via tanh: dice(x) = x * fma(C2, tanh(fma(x, S2, MS2)), A2)
__device__ __forceinline__ float dice4(float x, float4 c) {
    return x * fmaf(c.y, tanhx(fmaf(x, c.z, c.w)), c.x);
}
// m16n8k8 tf32 warp MMA (A row-major, B col-major, fp32 accum)
__device__ __forceinline__ void mma16n8k8(float& d0, float& d1, float& d2, float& d3,
                                          uint a0, uint a1, uint a2, uint a3,
                                          uint b0, uint b1) {
    asm("mma.sync.aligned.m16n8k8.row.col.f32.tf32.tf32.f32 "
        "{%0,%1,%2,%3}, {%4,%5,%6,%7}, {%8,%9}, {%0,%1,%2,%3};"
        : "+f"(d0), "+f"(d1), "+f"(d2), "+f"(d3)
        : "r"(a0), "r"(a1), "r"(a2), "r"(a3), "r"(b0), "r"(b1));
}
// slot interleave within each 8-index block: (8m+g, 8m+g+4) -> (8m+2g, 8m+2g+1)
__device__ __forceinline__ int slot_of(int c) {
    return (c & ~7) + 2 * (c & 3) + ((c >> 2) & 1);
}
// inverse of slot_of within each 8-block
__device__ __forceinline__ int unslot(int s) {
    return (s & ~7) + ((s & 7) >> 1) + 4 * (s & 1);
}

static constexpr int NT   = 416;     // 13 warps = 13 tiles
static constexpr int WROW = 88;      // W1c stride (conflict-free under LDS.64 phasing)
static constexpr int MROW = 24;      // Mtc stride

// ---- batch-independent precomputed images (written by setup_kernel) ----
__device__ float  g_W1c[40 * WROW];  // exact W1c shared image (tf32 bits)
__device__ float  g_Wk [80 * MROW];  // Mtc-layout image of W0[12+k][o]-W0[24+k][o]
__device__ float  g_Wq [80 * MROW];  // Mtc-layout image of W0[36+k][o]
__device__ float  g_Wbt[80 * 12];    // Wbt[o*12+i] = W0[i][o] + W0[24+i][o]
__device__ float4 g_cst[130];        // [0..79]=d0c, [80..119]=d1c, [120..129]=b1

__global__ void setup_kernel(
    const float* __restrict__ W0, const float* __restrict__ W1,
    const float* __restrict__ b1,
    const float* __restrict__ alpha0, const float* __restrict__ alpha1,
    const float* __restrict__ mm0, const float* __restrict__ mv0,
    const float* __restrict__ mm1, const float* __restrict__ mv1,
    const float* __restrict__ ak)
{
    const int tid = threadIdx.x;
    const float EPS = 1e-9f;
    // W1c image: row j (0..39) x 88 cols; col c<80 holds tf32(W1[unslot(c)][j])
    for (int idx = tid; idx < 40 * WROW; idx += 256) {
        int j = idx / WROW, c = idx % WROW;
        float v = 0.0f;
        if (c < 80) {
            int k = unslot(c);
            v = __uint_as_float(cvt_tf32(W1[k * 40 + j]));
        }
        g_W1c[idx] = v;
    }
    // Wk/Wq images in final Mtc layout: phys row po=slot(o), col s=slot(k); k>=12 -> 0
    for (int idx = tid; idx < 80 * MROW; idx += 256) {
        int po = idx / MROW, s = idx % MROW;
        int o = unslot(po);
        float wk = 0.0f, wq = 0.0f;
        if (s < 16) {
            int k = unslot(s);
            if (k < 12) {
                wk = W0[(12 + k) * 80 + o] - W0[(24 + k) * 80 + o];
                wq = W0[(36 + k) * 80 + o];
            }
        }
        g_Wk[idx] = wk;
        g_Wq[idx] = wq;
    }
    // Wbt transposed: Wbt[o*12+i] = W0[i][o] + W0[24+i][o]
    for (int idx = tid; idx < 960; idx += 256) {
        int o = idx / 12, i = idx % 12;
        g_Wbt[idx] = W0[i * 80 + o] + W0[(24 + i) * 80 + o];
    }
    // dice constants
    if (tid < 80) {
        float a  = alpha0[tid];
        float c2 = 0.5f * (1.0f - a);
        float s2 = 0.5f * rsqrtf(mv0[tid] + EPS);
        g_cst[tid] = make_float4(a + c2, c2, s2, -mm0[tid] * s2);
    }
    if (tid >= 128 && tid < 168) {
        int o = tid - 128;
        float a  = alpha1[o];
        float kk = ak[o];
        float c2 = 0.5f * (1.0f - a);
        float s2 = 0.5f * rsqrtf(mv1[o] + EPS);
        // h already includes b1 (folded into accumulator init)
        g_cst[80 + o] = make_float4((a + c2) * kk, c2 * kk, s2, -mm1[o] * s2);
    }
    if (tid >= 192 && tid < 202) {
        int p = tid - 192;
        g_cst[120 + p] = make_float4(b1[4*p], b1[4*p+1], b1[4*p+2], b1[4*p+3]);
    }
}

// Shared layout (floats):
static constexpr int O_KSH   = 0;                     // ksh [208][12]    2496
static constexpr int O_W1C   = 2496;                  // W1c [40][88]     3520
static constexpr int O_MTC   = O_W1C + 40*WROW;       // Mtc [80][24]     1920
static constexpr int O_CST   = O_MTC + 80*MROW;       // d0c|d1c|b1d      520
static constexpr int O_BASE  = O_CST + 520;           // base [80]        80
static constexpr int O_SC    = O_BASE + 80;           // sc [208]         208
static constexpr int O_PSUM  = O_SC + 208;            // psum [192]       192
static constexpr int O_QS    = O_PSUM + 192;          // qs [12]          12
static constexpr int O_QSLOT = O_QS + 12;             // qslot [24]       24
static constexpr int O_SC0   = O_QSLOT + 24;          // score0 (+pad)    4
static constexpr int SMEM_FLOATS = O_SC0 + 4;         // 8980
static constexpr int SMEM_BYTES  = SMEM_FLOATS * 4;   // 35920 B -> 3 CTAs/SM

__global__ void __launch_bounds__(NT, 3) din_kernel(
    const float* __restrict__ query, const float* __restrict__ keys,
    const float* __restrict__ b0, const float* __restrict__ ab,
    float* __restrict__ out)
{
    extern __shared__ __align__(16) float smf[];
    float*  ksh   = smf + O_KSH;     // keys natural [208][12], rows 200-207 zero
    float*  W1c   = smf + O_W1C;
    float*  Mtc   = smf + O_MTC;
    float4* d0c   = (float4*)(smf + O_CST);
    float4* d1c   = (float4*)(smf + O_CST + 320);
    float*  b1d   = smf + O_CST + 480;
    float*  basef = smf + O_BASE;
    float*  sc    = smf + O_SC;
    float*  psum  = smf + O_PSUM;
    float*  qs    = smf + O_QS;
    float*  qslot = smf + O_QSLOT;

    const int tid  = threadIdx.x;
    const int b    = blockIdx.x;
    const int wid  = tid >> 5;
    const int lane = tid & 31;
    const int g    = lane & 3;    // k/n group
    const int rw   = lane >> 2;   // row within fragment

    if (tid < 12) qs[tid] = query[b * 12 + tid];
    if (tid == 0) smf[O_SC0] = ab[0];
    __syncthreads();  // qs ready

    // ============ Phase A stage 1: copies + base + qslot ============
    {
        const float4* gk = (const float4*)(keys + (size_t)b * 2400);
        float4* sk = (float4*)ksh;
        for (int i = tid; i < 600; i += NT) sk[i] = gk[i];
        if (tid < 96) ksh[2400 + tid] = 0.0f;
    }
    {
        const float4* src = (const float4*)g_W1c;
        float4* dst = (float4*)W1c;
        for (int i = tid; i < (40 * WROW) / 4; i += NT) dst[i] = src[i];
    }
    if (tid < 130) ((float4*)(smf + O_CST))[tid] = g_cst[tid];
    if (tid < 24) {
        float v = 0.0f;
        if (tid < 16) { int k = unslot(tid); if (k < 12) v = qs[k]; }
        qslot[tid] = v;
    }
    if (tid < 80) {
        float s = b0[tid];
        const float4* wb = (const float4*)(g_Wbt + tid * 12);
        float4 w0v = wb[0], w1v = wb[1], w2v = wb[2];
        s += qs[0]*w0v.x + qs[1]*w0v.y + qs[2]*w0v.z  + qs[3]*w0v.w
           + qs[4]*w1v.x + qs[5]*w1v.y + qs[6]*w1v.z  + qs[7]*w1v.w
           + qs[8]*w2v.x + qs[9]*w2v.y + qs[10]*w2v.z + qs[11]*w2v.w;
        basef[tid] = s;
    }
    __syncthreads();

    // ============ Phase A stage 2: Mtc = cvt_tf32(Wk + q*Wq) ============
    for (int i = tid; i < 480; i += NT) {
        float4 wk = ((const float4*)g_Wk)[i];
        float4 wq = ((const float4*)g_Wq)[i];
        float4 q4 = ((const float4*)qslot)[i % 6];
        float4 v;
        v.x = __uint_as_float(cvt_tf32(fmaf(q4.x, wq.x, wk.x)));
        v.y = __uint_as_float(cvt_tf32(fmaf(q4.y, wq.y, wk.y)));
        v.z = __uint_as_float(cvt_tf32(fmaf(q4.z, wq.z, wk.z)));
        v.w = __uint_as_float(cvt_tf32(fmaf(q4.w, wq.w, wk.w)));
        ((float4*)Mtc)[i] = v;
    }
    __syncthreads();

    // ===== Fused tile (1 per warp): per jt: layer0 HMMA -> dice0 -> layer1 HMMA =
    // af[] array eliminated: each jt's diced output feeds its 5 layer-1 MMAs
    // immediately (jt is layer-1's k-tile index). Keeps peak live regs ~50.
    {
        const float score0 = smf[O_SC0];
        const int pt = wid;                       // 13 warps, 13 tiles
        const int r0 = pt * 16 + rw, r1 = r0 + 8;

        // k-fragments: raw fp32 bits (tf32 HMMA reads upper 19 bits = RZ trunc)
        const float* k0p = ksh + r0 * 12;
        const float* k1p = ksh + r1 * 12;
        uint ka0 = __float_as_uint(k0p[g]),     ka1 = __float_as_uint(k1p[g]);
        uint ka2 = __float_as_uint(k0p[g + 4]), ka3 = __float_as_uint(k1p[g + 4]);
        uint kb0 = __float_as_uint(k0p[8 + g]), kb1 = __float_as_uint(k1p[8 + g]);

        // layer-1 accumulators, b1 folded into init
        float hc[5][4];
        #pragma unroll
        for (int j5 = 0; j5 < 5; ++j5) {
            float2 bb = *(const float2*)(b1d + j5 * 8 + 2 * g);
            hc[j5][0] = bb.x; hc[j5][1] = bb.y;
            hc[j5][2] = bb.x; hc[j5][3] = bb.y;
        }

        const float* wbase = W1c + rw * WROW + 2 * g;
        #pragma unroll
        for (int jt = 0; jt < 10; ++jt) {
            // ---- layer 0 for channels 8jt+{g,g+4}, bias via acc init ----
            float bA = basef[8 * jt + g];
            float bB = basef[8 * jt + g + 4];
            float acc0 = bA, acc1 = bB, acc2 = bA, acc3 = bB;
            const float* mrow = Mtc + (jt * 8 + rw) * MROW + 2 * g;
            float2 w0 = *(const float2*)(mrow);       // logical k: g, g+4
            float2 w1 = *(const float2*)(mrow + 8);   // logical k: 8+g, (12+g -> 0)
            mma16n8k8(acc0, acc1, acc2, acc3, ka0, ka1, ka2, ka3,
                      __float_as_uint(w0.x), __float_as_uint(w0.y));
            mma16n8k8(acc0, acc1, acc2, acc3, kb0, kb1, 0u, 0u,
                      __float_as_uint(w1.x), __float_as_uint(w1.y));
            // ---- dice0 in-register (raw fp32 bits as tf32 A-frag) ----
            float4 ca = d0c[8 * jt + g];
            float4 cb = d0c[8 * jt + g + 4];
            uint af0 = __float_as_uint(dice4(acc0, ca));  // D[rw][8jt+g]
            uint af1 = __float_as_uint(dice4(acc2, ca));  // D[rw+8][8jt+g]
            uint af2 = __float_as_uint(dice4(acc1, cb));  // D[rw][8jt+g+4]
            uint af3 = __float_as_uint(dice4(acc3, cb));  // D[rw+8][8jt+g+4]
            // ---- layer 1 partial: this jt is layer-1 k-tile jt ----
            const float* wk = wbase + 8 * jt;
            #pragma unroll
            for (int j5 = 0; j5 < 5; ++j5) {
                float2 bw = *(const float2*)(wk + j5 * 8 * WROW);
                mma16n8k8(hc[j5][0], hc[j5][1], hc[j5][2], hc[j5][3],
                          af0, af1, af2, af3,
                          __float_as_uint(bw.x), __float_as_uint(bw.y));
            }
        }

        // ---- epilogue: dice1(+ak folded; h includes b1), row sums, reduce ----
        float s0 = 0.0f, s1 = 0.0f;
        #pragma unroll
        for (int j5 = 0; j5 < 5; ++j5) {
            const int ja = j5 * 8 + 2 * g;
            float4 ca = d1c[ja], cb = d1c[ja + 1];
            float c0 = hc[j5][0], c1 = hc[j5][1];
            float c2 = hc[j5][2], c3 = hc[j5][3];
            s0 = fmaf(c0, fmaf(ca.y, tanhx(fmaf(c0, ca.z, ca.w)), ca.x), s0);
            s0 = fmaf(c1, fmaf(cb.y, tanhx(fmaf(c1, cb.z, cb.w)), cb.x), s0);
            s1 = fmaf(c2, fmaf(ca.y, tanhx(fmaf(c2, ca.z, ca.w)), ca.x), s1);
            s1 = fmaf(c3, fmaf(cb.y, tanhx(fmaf(c3, cb.z, cb.w)), cb.x), s1);
        }
        s0 += __shfl_xor_sync(0xFFFFFFFF, s0, 1);
        s0 += __shfl_xor_sync(0xFFFFFFFF, s0, 2);
        s1 += __shfl_xor_sync(0xFFFFFFFF, s1, 1);
        s1 += __shfl_xor_sync(0xFFFFFFFF, s1, 2);
        if (g == 0) {
            sc[r0] = score0 + s0;
            sc[r1] = score0 + s1;
        }
    }
    __syncthreads();

    // ===================== Final: out[b][e] = sum_t sc[t] * keys[b][t][e] ======
    // (UNMASKED scores, reproducing the reference bug faithfully.)
    // Rows 200..207: ksh is zero there, so their products contribute 0.
    if (tid < 192) {
        int e = tid % 12;
        int c = tid / 12;     // 16 chunks of 13 positions (16*13 = 208)
        float acc = 0.0f;
        int t0 = c * 13;
        #pragma unroll
        for (int t2 = t0; t2 < t0 + 13; ++t2)
            acc = fmaf(sc[t2], ksh[t2 * 12 + e], acc);
        psum[tid] = acc;
    }
    __syncthreads();
    if (tid < 12) {
        float acc = 0.0f;
        #pragma unroll
        for (int c = 0; c < 16; ++c) acc += psum[c * 12 + tid];
        out[b * 12 + tid] = acc;
    }
}

extern "C" void kernel_launch(void* const* d_in, const int* in_sizes, int n_in,
                              void* d_out, int out_size) {
    const float* query  = (const float*)d_in[0];
    const float* keys   = (const float*)d_in[1];
    // d_in[2] = mask (bool) -- intentionally unused: reference overwrites the
    // masked scores and matmuls the UNMASKED scores (bug reproduced faithfully)
    const float* W0     = (const float*)d_in[3];
    const float* b0     = (const float*)d_in[4];
    const float* W1     = (const float*)d_in[5];
    const float* b1     = (const float*)d_in[6];
    const float* alpha0 = (const float*)d_in[7];
    const float* alpha1 = (const float*)d_in[8];
    const float* mm0    = (const float*)d_in[9];
    const float* mv0    = (const float*)d_in[10];
    const float* mm1    = (const float*)d_in[11];
    const float* mv1    = (const float*)d_in[12];
    const float* ak     = (const float*)d_in[13];
    const float* ab     = (const float*)d_in[14];
    float* out = (float*)d_out;

    // idempotent attribute set, not a stream op -> graph-capture safe
    cudaFuncSetAttribute(din_kernel, cudaFuncAttributeMaxDynamicSharedMemorySize,
                         SMEM_BYTES);

    // batch-independent precompute (deterministic; same stream -> ordered)
    setup_kernel<<<1, 256>>>(W0, W1, b1, alpha0, alpha1, mm0, mv0, mm1, mv1, ak);

    int B = out_size / 12;  // [B, 1, 12]
    din_kernel<<<B, NT, SMEM_BYTES>>>(query, keys, b0, ab, out);
}